// round 1
// baseline (speedup 1.0000x reference)
#include <cuda_runtime.h>
#include <math.h>

static constexpr int NT = 4096;   // tokens
static constexpr int DD = 1024;   // d_in == d_out

// Scratch (allocation-free rule: __device__ globals)
__device__ float g_Q[(size_t)NT * DD];
__device__ float g_K[(size_t)NT * DD];
__device__ float g_V[(size_t)NT * DD];
__device__ float g_S[(size_t)NT * NT];

// ---------------------------------------------------------------------------
// Tiled fp32 SGEMM: C[M,N] = alpha * A[M,K] @ op(B)
//   TRANSB=false: B is [K,N] row-major (NN)
//   TRANSB=true : B is [N,K] row-major, op(B)=B^T (NT; C[i,j] = sum_k A[i,k]*B[j,k])
// BM=BN=128, BK=8, 256 threads, 8x8 per-thread micro-tile.
// Requires M,N % 128 == 0 and K % 8 == 0 (true for all our shapes).
// ---------------------------------------------------------------------------
template <bool TRANSB>
__global__ __launch_bounds__(256, 2)
void sgemm128(const float* __restrict__ A, const float* __restrict__ B,
              float* __restrict__ C, int M, int N, int K, float alpha)
{
    constexpr int BM = 128, BN = 128, BK = 8, TM = 8, TN = 8;
    __shared__ float As[BK][BM];
    __shared__ float Bs[BK][BN];

    const int tid = threadIdx.x;           // 0..255
    const int bm  = blockIdx.y * BM;
    const int bn  = blockIdx.x * BN;
    const int tx  = tid & 15;              // 16 cols of threads
    const int ty  = tid >> 4;              // 16 rows of threads

    // A tile load: 128 rows x 8 cols; one float4 per thread along K
    const int aRow = tid >> 1;             // 0..127
    const int aCol = (tid & 1) * 4;        // 0 or 4
    // B tile load (NN): 8 rows x 128 cols; one float4 per thread along N
    const int bRow = tid >> 5;             // 0..7
    const int bCol = (tid & 31) * 4;       // 0..124

    float acc[TM][TN];
#pragma unroll
    for (int i = 0; i < TM; i++)
#pragma unroll
        for (int j = 0; j < TN; j++) acc[i][j] = 0.0f;

    for (int k0 = 0; k0 < K; k0 += BK) {
        // ---- load A tile (store transposed: As[k][m]) ----
        float4 av = *reinterpret_cast<const float4*>(&A[(size_t)(bm + aRow) * K + k0 + aCol]);
        As[aCol + 0][aRow] = av.x;
        As[aCol + 1][aRow] = av.y;
        As[aCol + 2][aRow] = av.z;
        As[aCol + 3][aRow] = av.w;

        // ---- load B tile (store as Bs[k][n]) ----
        if (!TRANSB) {
            float4 bv = *reinterpret_cast<const float4*>(&B[(size_t)(k0 + bRow) * N + bn + bCol]);
            *reinterpret_cast<float4*>(&Bs[bRow][bCol]) = bv;
        } else {
            // B is [N,K]; row bn+aRow, contiguous along K
            float4 bv = *reinterpret_cast<const float4*>(&B[(size_t)(bn + aRow) * K + k0 + aCol]);
            Bs[aCol + 0][aRow] = bv.x;
            Bs[aCol + 1][aRow] = bv.y;
            Bs[aCol + 2][aRow] = bv.z;
            Bs[aCol + 3][aRow] = bv.w;
        }
        __syncthreads();

#pragma unroll
        for (int kk = 0; kk < BK; kk++) {
            float ra[TM], rb[TN];
            // vectorized smem reads (two float4 each)
            float4 a0 = *reinterpret_cast<const float4*>(&As[kk][ty * TM]);
            float4 a1 = *reinterpret_cast<const float4*>(&As[kk][ty * TM + 4]);
            float4 b0 = *reinterpret_cast<const float4*>(&Bs[kk][tx * TN]);
            float4 b1 = *reinterpret_cast<const float4*>(&Bs[kk][tx * TN + 4]);
            ra[0]=a0.x; ra[1]=a0.y; ra[2]=a0.z; ra[3]=a0.w;
            ra[4]=a1.x; ra[5]=a1.y; ra[6]=a1.z; ra[7]=a1.w;
            rb[0]=b0.x; rb[1]=b0.y; rb[2]=b0.z; rb[3]=b0.w;
            rb[4]=b1.x; rb[5]=b1.y; rb[6]=b1.z; rb[7]=b1.w;
#pragma unroll
            for (int i = 0; i < TM; i++)
#pragma unroll
                for (int j = 0; j < TN; j++)
                    acc[i][j] = fmaf(ra[i], rb[j], acc[i][j]);
        }
        __syncthreads();
    }

    // ---- write back (two float4 per row of the micro-tile) ----
#pragma unroll
    for (int i = 0; i < TM; i++) {
        const int r = bm + ty * TM + i;
        float4 o0 = make_float4(acc[i][0] * alpha, acc[i][1] * alpha,
                                acc[i][2] * alpha, acc[i][3] * alpha);
        float4 o1 = make_float4(acc[i][4] * alpha, acc[i][5] * alpha,
                                acc[i][6] * alpha, acc[i][7] * alpha);
        *reinterpret_cast<float4*>(&C[(size_t)r * N + bn + tx * TN])     = o0;
        *reinterpret_cast<float4*>(&C[(size_t)r * N + bn + tx * TN + 4]) = o1;
    }
}

// ---------------------------------------------------------------------------
// In-place row softmax over S[4096][4096]. One block (256 threads) per row;
// row lives in registers (16 floats/thread).
// ---------------------------------------------------------------------------
__global__ __launch_bounds__(256)
void softmax4096(float* __restrict__ S)
{
    const int row = blockIdx.x;
    float* p = S + (size_t)row * NT;
    const int tid = threadIdx.x;
    constexpr int PT = NT / 256;   // 16

    float v[PT];
#pragma unroll
    for (int i = 0; i < PT; i++) v[i] = p[tid + i * 256];

    __shared__ float red[256];

    // --- max reduce ---
    float m = v[0];
#pragma unroll
    for (int i = 1; i < PT; i++) m = fmaxf(m, v[i]);
    red[tid] = m;
    __syncthreads();
#pragma unroll
    for (int s = 128; s > 0; s >>= 1) {
        if (tid < s) red[tid] = fmaxf(red[tid], red[tid + s]);
        __syncthreads();
    }
    m = red[0];
    __syncthreads();

    // --- exp + sum reduce ---
    float sum = 0.0f;
#pragma unroll
    for (int i = 0; i < PT; i++) {
        v[i] = expf(v[i] - m);
        sum += v[i];
    }
    red[tid] = sum;
    __syncthreads();
#pragma unroll
    for (int s = 128; s > 0; s >>= 1) {
        if (tid < s) red[tid] += red[tid + s];
        __syncthreads();
    }
    const float inv = 1.0f / red[0];

#pragma unroll
    for (int i = 0; i < PT; i++) p[tid + i * 256] = v[i] * inv;
}

// ---------------------------------------------------------------------------
// kernel_launch: x, w_query, w_key, w_value -> out
// ---------------------------------------------------------------------------
extern "C" void kernel_launch(void* const* d_in, const int* in_sizes, int n_in,
                              void* d_out, int out_size)
{
    const float* x  = (const float*)d_in[0];
    const float* wq = (const float*)d_in[1];
    const float* wk = (const float*)d_in[2];
    const float* wv = (const float*)d_in[3];
    float* out = (float*)d_out;

    float *Q, *K, *V, *S;
    cudaGetSymbolAddress((void**)&Q, g_Q);
    cudaGetSymbolAddress((void**)&K, g_K);
    cudaGetSymbolAddress((void**)&V, g_V);
    cudaGetSymbolAddress((void**)&S, g_S);

    const dim3 blk(256);

    // QKV projections: [4096,1024] = [4096,1024] @ [1024,1024]
    const dim3 gQKV(DD / 128, NT / 128);
    sgemm128<false><<<gQKV, blk>>>(x, wq, Q, NT, DD, DD, 1.0f);
    sgemm128<false><<<gQKV, blk>>>(x, wk, K, NT, DD, DD, 1.0f);
    sgemm128<false><<<gQKV, blk>>>(x, wv, V, NT, DD, DD, 1.0f);

    // scores: S = (Q @ K^T) / sqrt(1024)
    const dim3 gS(NT / 128, NT / 128);
    sgemm128<true><<<gS, blk>>>(Q, K, S, NT, NT, DD, 1.0f / 32.0f);

    // softmax rows
    softmax4096<<<NT, blk>>>(S);

    // out = P @ V : [4096,1024] = [4096,4096] @ [4096,1024]
    const dim3 gO(DD / 128, NT / 128);
    sgemm128<false><<<gO, blk>>>(S, V, out, NT, DD, NT, 1.0f);
}

// round 3
// speedup vs baseline: 2.5766x; 2.5766x over previous
#include <cuda_runtime.h>
#include <cuda_bf16.h>
#include <cstdint>

static constexpr int NT = 4096;   // tokens
static constexpr int DD = 1024;   // d_in == d_out

// ---------------- scratch (__device__ globals: allocation-free rule) --------
__device__ float g_QKV[(size_t)NT * 3 * DD];        // fused Q|K|V fp32
__device__ float g_S[(size_t)NT * NT];

__device__ __nv_bfloat16 g_xh[(size_t)NT * DD], g_xl[(size_t)NT * DD];
__device__ __nv_bfloat16 g_wh[(size_t)3 * DD * DD], g_wl[(size_t)3 * DD * DD]; // W^T cat
__device__ __nv_bfloat16 g_Qh[(size_t)NT * DD], g_Ql[(size_t)NT * DD];
__device__ __nv_bfloat16 g_Kh[(size_t)NT * DD], g_Kl[(size_t)NT * DD];
__device__ __nv_bfloat16 g_Vth[(size_t)DD * NT], g_Vtl[(size_t)DD * NT];       // V^T
__device__ __nv_bfloat16 g_Ph[(size_t)NT * NT], g_Pl[(size_t)NT * NT];

// ---------------- helpers ---------------------------------------------------
__device__ __forceinline__ uint32_t smem_u32(const void* p) {
    uint32_t a;
    asm("{ .reg .u64 t; cvta.to.shared.u64 t, %1; cvt.u32.u64 %0, t; }"
        : "=r"(a) : "l"(p));
    return a;
}

#define SWZ(o) ((o) ^ ((((uint32_t)(o)) >> 3) & 0x30))

__device__ __forceinline__ void cp16(uint32_t saddr, const void* gaddr) {
    asm volatile("cp.async.cg.shared.global [%0], [%1], 16;"
                 :: "r"(saddr), "l"(gaddr));
}

__device__ __forceinline__ void ldm_x4(uint32_t* r, uint32_t addr) {
    asm volatile("ldmatrix.sync.aligned.m8n8.x4.shared.b16 {%0,%1,%2,%3}, [%4];"
                 : "=r"(r[0]), "=r"(r[1]), "=r"(r[2]), "=r"(r[3]) : "r"(addr));
}

__device__ __forceinline__ void mma_bf16(float* c, const uint32_t* a, const uint32_t* b) {
    asm volatile(
        "mma.sync.aligned.m16n8k16.row.col.f32.bf16.bf16.f32 "
        "{%0,%1,%2,%3}, {%4,%5,%6,%7}, {%8,%9}, {%0,%1,%2,%3};"
        : "+f"(c[0]), "+f"(c[1]), "+f"(c[2]), "+f"(c[3])
        : "r"(a[0]), "r"(a[1]), "r"(a[2]), "r"(a[3]), "r"(b[0]), "r"(b[1]));
}

// ---------------------------------------------------------------------------
// Split-bf16 GEMM on the warp-MMA path:
//   C[M,N] = alpha * (A @ B^T), A = Ah+Al [M,K] row-major, B = Bh+Bl [N,K]
//   computed as Ah@Bh^T + Ah@Bl^T + Al@Bh^T, fp32 accumulators.
// BM=BN=128, BK=32, 256 threads, 2(m)x4(n) warps, 64x32 warp tile.
// Requires M,N % 128 == 0, K % 32 == 0.
// ---------------------------------------------------------------------------
static constexpr int TILE_B  = 128 * 64;        // 8 KB per operand tile (128 x 32 bf16)
static constexpr int STAGE_B = 4 * TILE_B;      // Ah, Al, Bh, Bl
static constexpr int SMEM_B  = 2 * STAGE_B;     // double buffer = 64 KB

__device__ __forceinline__ void issue_stage(
    uint32_t sb, int stage, int kchunk, int tid,
    const __nv_bfloat16* __restrict__ Ah, const __nv_bfloat16* __restrict__ Al,
    const __nv_bfloat16* __restrict__ Bh, const __nv_bfloat16* __restrict__ Bl,
    int bm, int bn, int K)
{
#pragma unroll
    for (int t = 0; t < 4; t++) {
        const __nv_bfloat16* src = (t == 0) ? Ah : (t == 1) ? Al : (t == 2) ? Bh : Bl;
        const int rb = (t < 2) ? bm : bn;
#pragma unroll
        for (int u = 0; u < 2; u++) {
            const int v = tid + 256 * u;            // 0..511
            const int row = v >> 2, c16 = v & 3;
            const uint32_t o = (uint32_t)(row * 64 + c16 * 16);
            cp16(sb + stage * STAGE_B + t * TILE_B + SWZ(o),
                 src + (size_t)(rb + row) * K + kchunk * 32 + c16 * 8);
        }
    }
    asm volatile("cp.async.commit_group;");
}

__global__ __launch_bounds__(256, 1)
void gemm_bf16x3(const __nv_bfloat16* __restrict__ Ah, const __nv_bfloat16* __restrict__ Al,
                 const __nv_bfloat16* __restrict__ Bh, const __nv_bfloat16* __restrict__ Bl,
                 float* __restrict__ C, int M, int N, int K, float alpha)
{
    extern __shared__ char smem[];
    const uint32_t sb = smem_u32(smem);
    const int tid  = threadIdx.x;
    const int wid  = tid >> 5;
    const int lane = tid & 31;
    const int bm = blockIdx.y * 128;
    const int bn = blockIdx.x * 128;
    const int wm = (wid >> 2) * 64;   // 0 | 64
    const int wn = (wid & 3) * 32;    // 0..96

    float acc[4][4][4];
#pragma unroll
    for (int i = 0; i < 4; i++)
#pragma unroll
        for (int j = 0; j < 4; j++)
#pragma unroll
            for (int r = 0; r < 4; r++) acc[i][j][r] = 0.0f;

    const int nc = K / 32;
    issue_stage(sb, 0, 0, tid, Ah, Al, Bh, Bl, bm, bn, K);
    issue_stage(sb, 1, 1, tid, Ah, Al, Bh, Bl, bm, bn, K);

    // per-lane ldmatrix address components
    const int arow   = lane & 15;
    const int achunk = lane >> 4;
    const int bsub   = lane >> 3;
    const int brow   = (lane & 7) + (bsub >> 1) * 8;
    const int bchunk = bsub & 1;

    for (int i = 0; i < nc; i++) {
        if (i < nc - 1) asm volatile("cp.async.wait_group 1;");
        else            asm volatile("cp.async.wait_group 0;");
        __syncthreads();

        const uint32_t base = sb + (i & 1) * STAGE_B;
#pragma unroll
        for (int s = 0; s < 2; s++) {
            uint32_t ah[4][4], al[4][4], bh[4][2], bl[4][2];
#pragma unroll
            for (int t = 0; t < 4; t++) {
                const uint32_t o = (uint32_t)((wm + t * 16 + arow) * 64 + s * 32 + achunk * 16);
                ldm_x4(ah[t], base + SWZ(o));
                ldm_x4(al[t], base + TILE_B + SWZ(o));
            }
#pragma unroll
            for (int g = 0; g < 2; g++) {
                const uint32_t o = (uint32_t)((wn + g * 16 + brow) * 64 + s * 32 + bchunk * 16);
                uint32_t r[4];
                ldm_x4(r, base + 2 * TILE_B + SWZ(o));
                bh[2 * g][0] = r[0]; bh[2 * g][1] = r[1];
                bh[2 * g + 1][0] = r[2]; bh[2 * g + 1][1] = r[3];
                ldm_x4(r, base + 3 * TILE_B + SWZ(o));
                bl[2 * g][0] = r[0]; bl[2 * g][1] = r[1];
                bl[2 * g + 1][0] = r[2]; bl[2 * g + 1][1] = r[3];
            }
#pragma unroll
            for (int mt = 0; mt < 4; mt++)
#pragma unroll
                for (int nt = 0; nt < 4; nt++) {
                    mma_bf16(acc[mt][nt], ah[mt], bh[nt]);
                    mma_bf16(acc[mt][nt], ah[mt], bl[nt]);
                    mma_bf16(acc[mt][nt], al[mt], bh[nt]);
                }
        }

        if (i + 2 < nc) {
            __syncthreads();
            issue_stage(sb, i & 1, i + 2, tid, Ah, Al, Bh, Bl, bm, bn, K);
        }
    }

    // epilogue
    const int r0 = bm + wm + (lane >> 2);
    const int c0 = bn + wn + (lane & 3) * 2;
#pragma unroll
    for (int mt = 0; mt < 4; mt++)
#pragma unroll
        for (int nt = 0; nt < 4; nt++) {
            const int row = r0 + mt * 16;
            const int col = c0 + nt * 8;
            float2 v0 = make_float2(acc[mt][nt][0] * alpha, acc[mt][nt][1] * alpha);
            float2 v1 = make_float2(acc[mt][nt][2] * alpha, acc[mt][nt][3] * alpha);
            *reinterpret_cast<float2*>(C + (size_t)row * N + col)       = v0;
            *reinterpret_cast<float2*>(C + (size_t)(row + 8) * N + col) = v1;
        }
}

// ---------------------------------------------------------------------------
// fp32 (strided rows) -> (hi, lo) bf16 split; 2 contiguous elems per thread.
// n = total elems of the [rows, DD] view; istride = input row stride.
// ---------------------------------------------------------------------------
__global__ __launch_bounds__(256)
void split_fp32(const float* __restrict__ in, int istride,
                __nv_bfloat16* __restrict__ hi, __nv_bfloat16* __restrict__ lo, int n)
{
    const int idx = (blockIdx.x * 256 + threadIdx.x) * 2;
    if (idx < n) {
        const int row = idx >> 10, col = idx & 1023;          // DD = 1024
        const float2 v = *reinterpret_cast<const float2*>(in + (size_t)row * istride + col);
        const __nv_bfloat16 h0 = __float2bfloat16(v.x);
        const __nv_bfloat16 h1 = __float2bfloat16(v.y);
        const __nv_bfloat16 l0 = __float2bfloat16(v.x - __bfloat162float(h0));
        const __nv_bfloat16 l1 = __float2bfloat16(v.y - __bfloat162float(h1));
        *reinterpret_cast<__nv_bfloat162*>(hi + idx) = __halves2bfloat162(h0, h1);
        *reinterpret_cast<__nv_bfloat162*>(lo + idx) = __halves2bfloat162(l0, l1);
    }
}

// ---------------------------------------------------------------------------
// fp32 [R, C] (row stride = istride) -> transposed (hi, lo) bf16 [C, R]
// ---------------------------------------------------------------------------
__global__ __launch_bounds__(256)
void tsplit_fp32(const float* __restrict__ in, int istride,
                 __nv_bfloat16* __restrict__ oh, __nv_bfloat16* __restrict__ ol,
                 int R, int C)
{
    __shared__ float t[32][33];
    const int bx = blockIdx.x * 32, by = blockIdx.y * 32;
    const int tx = threadIdx.x & 31, ty = threadIdx.x >> 5;   // 32x8
#pragma unroll
    for (int j = 0; j < 32; j += 8)
        t[ty + j][tx] = in[(size_t)(by + ty + j) * istride + bx + tx];
    __syncthreads();
#pragma unroll
    for (int j = 0; j < 32; j += 8) {
        const float v = t[tx][ty + j];
        const __nv_bfloat16 h = __float2bfloat16(v);
        const size_t o = (size_t)(bx + ty + j) * R + by + tx;
        oh[o] = h;
        ol[o] = __float2bfloat16(v - __bfloat162float(h));
    }
}

// ---------------------------------------------------------------------------
// Row softmax over S[4096][4096] + fused (hi, lo) bf16 split of P.
// ---------------------------------------------------------------------------
__global__ __launch_bounds__(256)
void softmax_split(const float* __restrict__ S, __nv_bfloat16* __restrict__ Ph,
                   __nv_bfloat16* __restrict__ Pl)
{
    const int row = blockIdx.x;
    const float* p = S + (size_t)row * NT;
    const int tid = threadIdx.x;
    const int base = tid * 16;

    float v[16];
#pragma unroll
    for (int q = 0; q < 4; q++) {
        const float4 x4 = *reinterpret_cast<const float4*>(p + base + q * 4);
        v[q * 4 + 0] = x4.x; v[q * 4 + 1] = x4.y; v[q * 4 + 2] = x4.z; v[q * 4 + 3] = x4.w;
    }

    __shared__ float red[256];
    float m = v[0];
#pragma unroll
    for (int q = 1; q < 16; q++) m = fmaxf(m, v[q]);
    red[tid] = m;
    __syncthreads();
#pragma unroll
    for (int s = 128; s > 0; s >>= 1) {
        if (tid < s) red[tid] = fmaxf(red[tid], red[tid + s]);
        __syncthreads();
    }
    m = red[0];
    __syncthreads();

    float sum = 0.0f;
#pragma unroll
    for (int q = 0; q < 16; q++) { v[q] = expf(v[q] - m); sum += v[q]; }
    red[tid] = sum;
    __syncthreads();
#pragma unroll
    for (int s = 128; s > 0; s >>= 1) {
        if (tid < s) red[tid] += red[tid + s];
        __syncthreads();
    }
    const float inv = 1.0f / red[0];

    __nv_bfloat16* ph = Ph + (size_t)row * NT + base;
    __nv_bfloat16* pl = Pl + (size_t)row * NT + base;
#pragma unroll
    for (int q = 0; q < 8; q++) {
        const float a = v[2 * q] * inv;
        const float b = v[2 * q + 1] * inv;
        const __nv_bfloat16 h0 = __float2bfloat16(a);
        const __nv_bfloat16 h1 = __float2bfloat16(b);
        const __nv_bfloat16 l0 = __float2bfloat16(a - __bfloat162float(h0));
        const __nv_bfloat16 l1 = __float2bfloat16(b - __bfloat162float(h1));
        *reinterpret_cast<__nv_bfloat162*>(ph + 2 * q) = __halves2bfloat162(h0, h1);
        *reinterpret_cast<__nv_bfloat162*>(pl + 2 * q) = __halves2bfloat162(l0, l1);
    }
}

// ---------------------------------------------------------------------------
// kernel_launch
// ---------------------------------------------------------------------------
extern "C" void kernel_launch(void* const* d_in, const int* in_sizes, int n_in,
                              void* d_out, int out_size)
{
    const float* x  = (const float*)d_in[0];
    const float* wq = (const float*)d_in[1];
    const float* wk = (const float*)d_in[2];
    const float* wv = (const float*)d_in[3];
    float* out = (float*)d_out;

    float *QKV, *S;
    __nv_bfloat16 *xh, *xl, *wh, *wl, *Qh, *Ql, *Kh, *Kl, *Vth, *Vtl, *Ph, *Pl;
    cudaGetSymbolAddress((void**)&QKV, g_QKV);
    cudaGetSymbolAddress((void**)&S, g_S);
    cudaGetSymbolAddress((void**)&xh, g_xh);
    cudaGetSymbolAddress((void**)&xl, g_xl);
    cudaGetSymbolAddress((void**)&wh, g_wh);
    cudaGetSymbolAddress((void**)&wl, g_wl);
    cudaGetSymbolAddress((void**)&Qh, g_Qh);
    cudaGetSymbolAddress((void**)&Ql, g_Ql);
    cudaGetSymbolAddress((void**)&Kh, g_Kh);
    cudaGetSymbolAddress((void**)&Kl, g_Kl);
    cudaGetSymbolAddress((void**)&Vth, g_Vth);
    cudaGetSymbolAddress((void**)&Vtl, g_Vtl);
    cudaGetSymbolAddress((void**)&Ph, g_Ph);
    cudaGetSymbolAddress((void**)&Pl, g_Pl);

    cudaFuncSetAttribute(gemm_bf16x3, cudaFuncAttributeMaxDynamicSharedMemorySize, SMEM_B);

    const size_t WW = (size_t)DD * DD;
    const dim3 blk(256);

    // 1) operand prep: split x, transpose+split weights into cat-[3072,1024]
    split_fp32<<<NT * DD / 512, blk>>>(x, DD, xh, xl, NT * DD);
    {
        const dim3 g(DD / 32, DD / 32);
        tsplit_fp32<<<g, blk>>>(wq, DD, wh + 0 * WW, wl + 0 * WW, DD, DD);
        tsplit_fp32<<<g, blk>>>(wk, DD, wh + 1 * WW, wl + 1 * WW, DD, DD);
        tsplit_fp32<<<g, blk>>>(wv, DD, wh + 2 * WW, wl + 2 * WW, DD, DD);
    }

    // 2) fused projections: QKV[4096,3072] = x @ [Wq|Wk|Wv]
    gemm_bf16x3<<<dim3(3 * DD / 128, NT / 128), blk, SMEM_B>>>(
        xh, xl, wh, wl, QKV, NT, 3 * DD, DD, 1.0f);

    // 3) extract + split attention operands
    split_fp32<<<NT * DD / 512, blk>>>(QKV + 0 * DD, 3 * DD, Qh, Ql, NT * DD);
    split_fp32<<<NT * DD / 512, blk>>>(QKV + 1 * DD, 3 * DD, Kh, Kl, NT * DD);
    tsplit_fp32<<<dim3(DD / 32, NT / 32), blk>>>(QKV + 2 * DD, 3 * DD, Vth, Vtl, NT, DD);

    // 4) scores: S = (Q @ K^T) / 32
    gemm_bf16x3<<<dim3(NT / 128, NT / 128), blk, SMEM_B>>>(
        Qh, Ql, Kh, Kl, S, NT, NT, DD, 1.0f / 32.0f);

    // 5) softmax + split P
    softmax_split<<<NT, blk>>>(S, Ph, Pl);

    // 6) out = P @ V  (B operand = V^T [1024, 4096])
    gemm_bf16x3<<<dim3(DD / 128, NT / 128), blk, SMEM_B>>>(
        Ph, Pl, Vth, Vtl, out, NT, DD, NT, 1.0f);
}

// round 4
// speedup vs baseline: 2.7939x; 1.0843x over previous
#include <cuda_runtime.h>
#include <cuda_bf16.h>
#include <cuda_fp16.h>
#include <cstdint>

static constexpr int NT = 4096;   // tokens
static constexpr int DD = 1024;   // d_in == d_out

// ---------------- scratch (__device__ globals: allocation-free rule) --------
__device__ float g_V[(size_t)NT * DD];              // fp32 V from proj epilogue
__device__ float g_S[(size_t)NT * NT];              // fp32 scores

__device__ __nv_bfloat16 g_xh[(size_t)NT * DD], g_xl[(size_t)NT * DD];
__device__ __nv_bfloat16 g_wh[(size_t)3 * DD * DD], g_wl[(size_t)3 * DD * DD]; // cat W^T
__device__ __nv_bfloat16 g_Qh[(size_t)NT * DD], g_Ql[(size_t)NT * DD];
__device__ __nv_bfloat16 g_Kh[(size_t)NT * DD], g_Kl[(size_t)NT * DD];
__device__ __half g_Vth[(size_t)DD * NT], g_Vtl[(size_t)DD * NT];              // V^T fp16
__device__ __half g_Ph[(size_t)NT * NT];                                       // P fp16

// ---------------- helpers ---------------------------------------------------
__device__ __forceinline__ uint32_t smem_u32(const void* p) {
    uint32_t a;
    asm("{ .reg .u64 t; cvta.to.shared.u64 t, %1; cvt.u32.u64 %0, t; }"
        : "=r"(a) : "l"(p));
    return a;
}

#define SWZ(o) ((o) ^ ((((uint32_t)(o)) >> 3) & 0x30))

__device__ __forceinline__ void cp16(uint32_t saddr, const void* gaddr) {
    asm volatile("cp.async.cg.shared.global [%0], [%1], 16;"
                 :: "r"(saddr), "l"(gaddr));
}

__device__ __forceinline__ void ldm_x4(uint32_t* r, uint32_t addr) {
    asm volatile("ldmatrix.sync.aligned.m8n8.x4.shared.b16 {%0,%1,%2,%3}, [%4];"
                 : "=r"(r[0]), "=r"(r[1]), "=r"(r[2]), "=r"(r[3]) : "r"(addr));
}

__device__ __forceinline__ void mma_bf16(float* c, const uint32_t* a, const uint32_t* b) {
    asm volatile(
        "mma.sync.aligned.m16n8k16.row.col.f32.bf16.bf16.f32 "
        "{%0,%1,%2,%3}, {%4,%5,%6,%7}, {%8,%9}, {%0,%1,%2,%3};"
        : "+f"(c[0]), "+f"(c[1]), "+f"(c[2]), "+f"(c[3])
        : "r"(a[0]), "r"(a[1]), "r"(a[2]), "r"(a[3]), "r"(b[0]), "r"(b[1]));
}

__device__ __forceinline__ void mma_f16(float* c, const uint32_t* a, const uint32_t* b) {
    asm volatile(
        "mma.sync.aligned.m16n8k16.row.col.f32.f16.f16.f32 "
        "{%0,%1,%2,%3}, {%4,%5,%6,%7}, {%8,%9}, {%0,%1,%2,%3};"
        : "+f"(c[0]), "+f"(c[1]), "+f"(c[2]), "+f"(c[3])
        : "r"(a[0]), "r"(a[1]), "r"(a[2]), "r"(a[3]), "r"(b[0]), "r"(b[1]));
}

__device__ __forceinline__ void split_store_bf16(
    __nv_bfloat16* H, __nv_bfloat16* L, size_t idx, float a, float b)
{
    const __nv_bfloat16 h0 = __float2bfloat16(a);
    const __nv_bfloat16 h1 = __float2bfloat16(b);
    const __nv_bfloat16 l0 = __float2bfloat16(a - __bfloat162float(h0));
    const __nv_bfloat16 l1 = __float2bfloat16(b - __bfloat162float(h1));
    *reinterpret_cast<__nv_bfloat162*>(H + idx) = __halves2bfloat162(h0, h1);
    *reinterpret_cast<__nv_bfloat162*>(L + idx) = __halves2bfloat162(l0, l1);
}

// ---------------------------------------------------------------------------
// Warp-MMA split GEMM, 3-stage cp.async pipeline.
//   MODE 0: C = alpha*(A@B^T); A=Ah+Al bf16 [M,K], B=Bh+Bl bf16 [N,K]; 3 terms.
//   MODE 1: C = A@B^T;        A=Ah fp16 [M,K], B=Bh+Bl fp16 [N,K]; 2 terms.
//   MODE 2: like 0, but proj epilogue: N=3072 cat; writes Qh/Ql, Kh/Kl, g_V.
// BM=BN=128, BK=32, 256 threads, 2(m)x4(n) warps, 64x32 warp tile.
// ---------------------------------------------------------------------------
static constexpr int TILE_B = 128 * 64;   // 8 KB (128 rows x 32 elems x 2B)

template <int MODE>
__global__ __launch_bounds__(256, 1)
void gemm_mma(const void* __restrict__ A0, const void* __restrict__ A1,
              const void* __restrict__ B0, const void* __restrict__ B1,
              float* __restrict__ C, int M, int N, int K, float alpha)
{
    constexpr int NTILES  = (MODE == 1) ? 3 : 4;
    constexpr int STAGE_B = NTILES * TILE_B;

    extern __shared__ char smem[];
    const uint32_t sb = smem_u32(smem);
    const int tid  = threadIdx.x;
    const int wid  = tid >> 5;
    const int lane = tid & 31;
    const int bm = blockIdx.y * 128;
    const int bn = blockIdx.x * 128;
    const int wm = (wid >> 2) * 64;
    const int wn = (wid & 3) * 32;

    const char* srcs[4];
    int rbs[4];
    if (MODE == 1) {
        srcs[0] = (const char*)A0; rbs[0] = bm;
        srcs[1] = (const char*)B0; rbs[1] = bn;
        srcs[2] = (const char*)B1; rbs[2] = bn;
        srcs[3] = nullptr;         rbs[3] = 0;
    } else {
        srcs[0] = (const char*)A0; rbs[0] = bm;
        srcs[1] = (const char*)A1; rbs[1] = bm;
        srcs[2] = (const char*)B0; rbs[2] = bn;
        srcs[3] = (const char*)B1; rbs[3] = bn;
    }

    auto issue = [&](int stage, int kchunk) {
#pragma unroll
        for (int t = 0; t < NTILES; t++) {
#pragma unroll
            for (int u = 0; u < 2; u++) {
                const int v = tid + 256 * u;         // 0..511
                const int row = v >> 2, c16 = v & 3;
                const uint32_t o = (uint32_t)(row * 64 + c16 * 16);
                cp16(sb + stage * STAGE_B + t * TILE_B + SWZ(o),
                     srcs[t] + ((size_t)(rbs[t] + row) * K + kchunk * 32) * 2 + c16 * 16);
            }
        }
        asm volatile("cp.async.commit_group;");
    };

    float acc[4][4][4];
#pragma unroll
    for (int i = 0; i < 4; i++)
#pragma unroll
        for (int j = 0; j < 4; j++)
#pragma unroll
            for (int r = 0; r < 4; r++) acc[i][j][r] = 0.0f;

    const int nc = K / 32;
    issue(0, 0);
    issue(1, 1);

    const int arow   = lane & 15;
    const int achunk = lane >> 4;
    const int bsub   = lane >> 3;
    const int brow   = (lane & 7) + (bsub >> 1) * 8;
    const int bchunk = bsub & 1;

    for (int i = 0; i < nc; i++) {
        if (i < nc - 1) asm volatile("cp.async.wait_group 1;");
        else            asm volatile("cp.async.wait_group 0;");
        __syncthreads();

        if (i + 2 < nc) issue((i + 2) % 3, i + 2);

        const uint32_t base = sb + (i % 3) * STAGE_B;
#pragma unroll
        for (int s = 0; s < 2; s++) {
            uint32_t a0[4][4], a1[4][4], b0r[4][2], b1r[4][2];
#pragma unroll
            for (int t = 0; t < 4; t++) {
                const uint32_t o = (uint32_t)((wm + t * 16 + arow) * 64 + s * 32 + achunk * 16);
                ldm_x4(a0[t], base + SWZ(o));
                if (MODE != 1) ldm_x4(a1[t], base + TILE_B + SWZ(o));
            }
            const int bt0 = (MODE == 1) ? 1 : 2;
#pragma unroll
            for (int g = 0; g < 2; g++) {
                const uint32_t o = (uint32_t)((wn + g * 16 + brow) * 64 + s * 32 + bchunk * 16);
                uint32_t r[4];
                ldm_x4(r, base + bt0 * TILE_B + SWZ(o));
                b0r[2 * g][0] = r[0]; b0r[2 * g][1] = r[1];
                b0r[2 * g + 1][0] = r[2]; b0r[2 * g + 1][1] = r[3];
                ldm_x4(r, base + (bt0 + 1) * TILE_B + SWZ(o));
                b1r[2 * g][0] = r[0]; b1r[2 * g][1] = r[1];
                b1r[2 * g + 1][0] = r[2]; b1r[2 * g + 1][1] = r[3];
            }
#pragma unroll
            for (int mt = 0; mt < 4; mt++)
#pragma unroll
                for (int nt = 0; nt < 4; nt++) {
                    if (MODE == 1) {
                        mma_f16(acc[mt][nt], a0[mt], b0r[nt]);
                        mma_f16(acc[mt][nt], a0[mt], b1r[nt]);
                    } else {
                        mma_bf16(acc[mt][nt], a0[mt], b0r[nt]);
                        mma_bf16(acc[mt][nt], a0[mt], b1r[nt]);
                        mma_bf16(acc[mt][nt], a1[mt], b0r[nt]);
                    }
                }
        }
    }

    // ---- epilogue ----
    const int r0 = bm + wm + (lane >> 2);
    const int c0 = wn + (lane & 3) * 2;          // col within the 128-wide tile

    if (MODE == 2) {
        const int region = bn >> 10;             // 0=Q, 1=K, 2=V (tile never straddles)
        const int cb = bn & 1023;
#pragma unroll
        for (int mt = 0; mt < 4; mt++)
#pragma unroll
            for (int nt = 0; nt < 4; nt++) {
                const int row = r0 + mt * 16;
                const int col = cb + c0 + nt * 8;
                const size_t i0 = (size_t)row * DD + col;
                const size_t i1 = (size_t)(row + 8) * DD + col;
                if (region == 0) {
                    split_store_bf16(g_Qh, g_Ql, i0, acc[mt][nt][0], acc[mt][nt][1]);
                    split_store_bf16(g_Qh, g_Ql, i1, acc[mt][nt][2], acc[mt][nt][3]);
                } else if (region == 1) {
                    split_store_bf16(g_Kh, g_Kl, i0, acc[mt][nt][0], acc[mt][nt][1]);
                    split_store_bf16(g_Kh, g_Kl, i1, acc[mt][nt][2], acc[mt][nt][3]);
                } else {
                    *reinterpret_cast<float2*>(g_V + i0) =
                        make_float2(acc[mt][nt][0], acc[mt][nt][1]);
                    *reinterpret_cast<float2*>(g_V + i1) =
                        make_float2(acc[mt][nt][2], acc[mt][nt][3]);
                }
            }
    } else {
#pragma unroll
        for (int mt = 0; mt < 4; mt++)
#pragma unroll
            for (int nt = 0; nt < 4; nt++) {
                const int row = r0 + mt * 16;
                const int col = bn + c0 + nt * 8;
                *reinterpret_cast<float2*>(C + (size_t)row * N + col) =
                    make_float2(acc[mt][nt][0] * alpha, acc[mt][nt][1] * alpha);
                *reinterpret_cast<float2*>(C + (size_t)(row + 8) * N + col) =
                    make_float2(acc[mt][nt][2] * alpha, acc[mt][nt][3] * alpha);
            }
    }
}

// ---------------------------------------------------------------------------
// fp32 -> (hi, lo) bf16 split, contiguous
// ---------------------------------------------------------------------------
__global__ __launch_bounds__(256)
void split_fp32(const float* __restrict__ in, __nv_bfloat16* __restrict__ hi,
                __nv_bfloat16* __restrict__ lo, int n)
{
    const int idx = (blockIdx.x * 256 + threadIdx.x) * 2;
    if (idx < n) {
        const float2 v = *reinterpret_cast<const float2*>(in + idx);
        split_store_bf16(hi, lo, idx, v.x, v.y);
    }
}

// ---------------------------------------------------------------------------
// fp32 [R,C] -> transposed (hi,lo) bf16 [C,R]   (weights W -> W^T)
// ---------------------------------------------------------------------------
__global__ __launch_bounds__(256)
void tsplit_bf16(const float* __restrict__ in,
                 __nv_bfloat16* __restrict__ oh, __nv_bfloat16* __restrict__ ol,
                 int R, int C)
{
    __shared__ float t[32][33];
    const int bx = blockIdx.x * 32, by = blockIdx.y * 32;
    const int tx = threadIdx.x & 31, ty = threadIdx.x >> 5;
#pragma unroll
    for (int j = 0; j < 32; j += 8)
        t[ty + j][tx] = in[(size_t)(by + ty + j) * C + bx + tx];
    __syncthreads();
#pragma unroll
    for (int j = 0; j < 32; j += 8) {
        const float v = t[tx][ty + j];
        const __nv_bfloat16 h = __float2bfloat16(v);
        const size_t o = (size_t)(bx + ty + j) * R + by + tx;
        oh[o] = h;
        ol[o] = __float2bfloat16(v - __bfloat162float(h));
    }
}

// ---------------------------------------------------------------------------
// fp32 V [NT,DD] -> transposed (hi,lo) fp16 V^T [DD,NT]
// ---------------------------------------------------------------------------
__global__ __launch_bounds__(256)
void tsplit_f16(const float* __restrict__ in,
                __half* __restrict__ oh, __half* __restrict__ ol, int R, int C)
{
    __shared__ float t[32][33];
    const int bx = blockIdx.x * 32, by = blockIdx.y * 32;
    const int tx = threadIdx.x & 31, ty = threadIdx.x >> 5;
#pragma unroll
    for (int j = 0; j < 32; j += 8)
        t[ty + j][tx] = in[(size_t)(by + ty + j) * C + bx + tx];
    __syncthreads();
#pragma unroll
    for (int j = 0; j < 32; j += 8) {
        const float v = t[tx][ty + j];
        const __half h = __float2half_rn(v);
        const size_t o = (size_t)(bx + ty + j) * R + by + tx;
        oh[o] = h;
        ol[o] = __float2half_rn(v - __half2float(h));
    }
}

// ---------------------------------------------------------------------------
// Row softmax over S[4096][4096] -> P fp16
// ---------------------------------------------------------------------------
__global__ __launch_bounds__(256)
void softmax_f16(const float* __restrict__ S, __half* __restrict__ Ph)
{
    const int row = blockIdx.x;
    const float* p = S + (size_t)row * NT;
    const int tid = threadIdx.x;
    const int base = tid * 16;

    float v[16];
#pragma unroll
    for (int q = 0; q < 4; q++) {
        const float4 x4 = *reinterpret_cast<const float4*>(p + base + q * 4);
        v[q * 4 + 0] = x4.x; v[q * 4 + 1] = x4.y; v[q * 4 + 2] = x4.z; v[q * 4 + 3] = x4.w;
    }

    __shared__ float red[256];
    float m = v[0];
#pragma unroll
    for (int q = 1; q < 16; q++) m = fmaxf(m, v[q]);
    red[tid] = m;
    __syncthreads();
#pragma unroll
    for (int s = 128; s > 0; s >>= 1) {
        if (tid < s) red[tid] = fmaxf(red[tid], red[tid + s]);
        __syncthreads();
    }
    m = red[0];
    __syncthreads();

    float sum = 0.0f;
#pragma unroll
    for (int q = 0; q < 16; q++) { v[q] = expf(v[q] - m); sum += v[q]; }
    red[tid] = sum;
    __syncthreads();
#pragma unroll
    for (int s = 128; s > 0; s >>= 1) {
        if (tid < s) red[tid] += red[tid + s];
        __syncthreads();
    }
    const float inv = 1.0f / red[0];

    __half* ph = Ph + (size_t)row * NT + base;
#pragma unroll
    for (int q = 0; q < 8; q++) {
        *reinterpret_cast<__half2*>(ph + 2 * q) =
            __floats2half2_rn(v[2 * q] * inv, v[2 * q + 1] * inv);
    }
}

// ---------------------------------------------------------------------------
// kernel_launch
// ---------------------------------------------------------------------------
extern "C" void kernel_launch(void* const* d_in, const int* in_sizes, int n_in,
                              void* d_out, int out_size)
{
    const float* x  = (const float*)d_in[0];
    const float* wq = (const float*)d_in[1];
    const float* wk = (const float*)d_in[2];
    const float* wv = (const float*)d_in[3];
    float* out = (float*)d_out;

    float *V, *S;
    __nv_bfloat16 *xh, *xl, *wh, *wl, *Qh, *Ql, *Kh, *Kl;
    __half *Vth, *Vtl, *Ph;
    cudaGetSymbolAddress((void**)&V, g_V);
    cudaGetSymbolAddress((void**)&S, g_S);
    cudaGetSymbolAddress((void**)&xh, g_xh);
    cudaGetSymbolAddress((void**)&xl, g_xl);
    cudaGetSymbolAddress((void**)&wh, g_wh);
    cudaGetSymbolAddress((void**)&wl, g_wl);
    cudaGetSymbolAddress((void**)&Qh, g_Qh);
    cudaGetSymbolAddress((void**)&Ql, g_Ql);
    cudaGetSymbolAddress((void**)&Kh, g_Kh);
    cudaGetSymbolAddress((void**)&Kl, g_Kl);
    cudaGetSymbolAddress((void**)&Vth, g_Vth);
    cudaGetSymbolAddress((void**)&Vtl, g_Vtl);
    cudaGetSymbolAddress((void**)&Ph, g_Ph);

    static bool attr_done = false;
    if (!attr_done) {
        cudaFuncSetAttribute(gemm_mma<0>, cudaFuncAttributeMaxDynamicSharedMemorySize,
                             3 * 4 * TILE_B);
        cudaFuncSetAttribute(gemm_mma<1>, cudaFuncAttributeMaxDynamicSharedMemorySize,
                             3 * 3 * TILE_B);
        cudaFuncSetAttribute(gemm_mma<2>, cudaFuncAttributeMaxDynamicSharedMemorySize,
                             3 * 4 * TILE_B);
        attr_done = true;
    }

    const size_t WW = (size_t)DD * DD;
    const dim3 blk(256);

    // 1) prep: split x, transpose+split weights (cat [3072,1024] row-major = W^T)
    split_fp32<<<NT * DD / 512, blk>>>(x, xh, xl, NT * DD);
    {
        const dim3 g(DD / 32, DD / 32);
        tsplit_bf16<<<g, blk>>>(wq, wh + 0 * WW, wl + 0 * WW, DD, DD);
        tsplit_bf16<<<g, blk>>>(wk, wh + 1 * WW, wl + 1 * WW, DD, DD);
        tsplit_bf16<<<g, blk>>>(wv, wh + 2 * WW, wl + 2 * WW, DD, DD);
    }

    // 2) fused projections (epilogue writes Qh/Ql, Kh/Kl bf16 + V fp32)
    gemm_mma<2><<<dim3(3 * DD / 128, NT / 128), blk, 3 * 4 * TILE_B>>>(
        xh, xl, wh, wl, nullptr, NT, 3 * DD, DD, 1.0f);

    // 3) V^T fp16 split
    tsplit_f16<<<dim3(DD / 32, NT / 32), blk>>>(V, Vth, Vtl, NT, DD);

    // 4) scores: S = (Q @ K^T) / 32   (bf16 3-term)
    gemm_mma<0><<<dim3(NT / 128, NT / 128), blk, 3 * 4 * TILE_B>>>(
        Qh, Ql, Kh, Kl, S, NT, NT, DD, 1.0f / 32.0f);

    // 5) softmax -> P fp16
    softmax_f16<<<NT, blk>>>(S, Ph);

    // 6) out = P @ V   (fp16 2-term; B = V^T [1024, 4096])
    gemm_mma<1><<<dim3(DD / 128, NT / 128), blk, 3 * 3 * TILE_B>>>(
        Ph, nullptr, Vth, Vtl, out, NT, DD, NT, 1.0f);
}

// round 6
// speedup vs baseline: 3.3976x; 1.2161x over previous
#include <cuda_runtime.h>
#include <cuda_fp16.h>
#include <cstdint>

static constexpr int NT = 4096;   // tokens
static constexpr int DD = 1024;   // d_in == d_out

// ---------------- scratch (__device__ globals: allocation-free rule) --------
__device__ float g_V[(size_t)NT * DD];              // fp32 V from proj epilogue
__device__ float g_S[(size_t)NT * NT];              // fp32 scores

__device__ __half g_xh[(size_t)NT * DD], g_xl[(size_t)NT * DD];
__device__ __half g_wh[(size_t)3 * DD * DD], g_wl[(size_t)3 * DD * DD];   // cat W^T
__device__ __half g_Qh[(size_t)NT * DD], g_Ql[(size_t)NT * DD];
__device__ __half g_Kh[(size_t)NT * DD], g_Kl[(size_t)NT * DD];
__device__ __half g_Vth[(size_t)DD * NT], g_Vtl[(size_t)DD * NT];         // V^T
__device__ __half g_Ph[(size_t)NT * NT];                                  // P fp16

// ---------------- helpers ---------------------------------------------------
__device__ __forceinline__ uint32_t smem_u32(const void* p) {
    uint32_t a;
    asm("{ .reg .u64 t; cvta.to.shared.u64 t, %1; cvt.u32.u64 %0, t; }"
        : "=r"(a) : "l"(p));
    return a;
}

// 128B-row swizzle: XOR 16B-chunk index (bits 4-6) with row%8 (bits 7-9)
#define SWZ(o) ((o) ^ ((((uint32_t)(o)) >> 3) & 0x70))

__device__ __forceinline__ void cp16(uint32_t saddr, const void* gaddr) {
    asm volatile("cp.async.cg.shared.global [%0], [%1], 16;"
                 :: "r"(saddr), "l"(gaddr));
}

__device__ __forceinline__ void ldm_x4(uint32_t* r, uint32_t addr) {
    asm volatile("ldmatrix.sync.aligned.m8n8.x4.shared.b16 {%0,%1,%2,%3}, [%4];"
                 : "=r"(r[0]), "=r"(r[1]), "=r"(r[2]), "=r"(r[3]) : "r"(addr));
}

__device__ __forceinline__ void mma_f16(float* c, const uint32_t* a, const uint32_t* b) {
    asm volatile(
        "mma.sync.aligned.m16n8k16.row.col.f32.f16.f16.f32 "
        "{%0,%1,%2,%3}, {%4,%5,%6,%7}, {%8,%9}, {%0,%1,%2,%3};"
        : "+f"(c[0]), "+f"(c[1]), "+f"(c[2]), "+f"(c[3])
        : "r"(a[0]), "r"(a[1]), "r"(a[2]), "r"(a[3]), "r"(b[0]), "r"(b[1]));
}

__device__ __forceinline__ void split_store_f16(
    __half* H, __half* L, size_t idx, float a, float b)
{
    const __half h0 = __float2half_rn(a);
    const __half h1 = __float2half_rn(b);
    const __half l0 = __float2half_rn(a - __half2float(h0));
    const __half l1 = __float2half_rn(b - __half2float(h1));
    *reinterpret_cast<__half2*>(H + idx) = __halves2half2(h0, h1);
    *reinterpret_cast<__half2*>(L + idx) = __halves2half2(l0, l1);
}

// ---------------------------------------------------------------------------
// Warp-MMA split-fp16 GEMM, BK=64, 3-stage cp.async pipeline.
//   MODE 0 (scores): C = alpha*(A@B^T); 3 terms A0B0+A0B1+A1B0.
//   MODE 1 (PV):     C = A@B^T; 2 terms A0B0+A0B1; tiles A0,B0,B1.
//   MODE 2 (proj):   3 terms; epilogue writes Qh/Ql, Kh/Kl splits + g_V fp32.
// BM=BN=128, BK=64, 256 threads, 2(m)x4(n) warps, 64x32 warp tile.
// ---------------------------------------------------------------------------
static constexpr int TILE_B = 128 * 128;   // 16 KB (128 rows x 64 fp16)

template <int MODE>
__global__ __launch_bounds__(256, 1)
void gemm_mma(const __half* __restrict__ A0, const __half* __restrict__ A1,
              const __half* __restrict__ B0, const __half* __restrict__ B1,
              float* __restrict__ C, int M, int N, int K, float alpha)
{
    constexpr int NTILES  = (MODE == 1) ? 3 : 4;
    constexpr int STAGE_B = NTILES * TILE_B;

    extern __shared__ char smem[];
    const uint32_t sb = smem_u32(smem);
    const int tid  = threadIdx.x;
    const int wid  = tid >> 5;
    const int lane = tid & 31;
    const int bm = blockIdx.y * 128;
    const int bn = blockIdx.x * 128;
    const int wm = (wid >> 2) * 64;
    const int wn = (wid & 3) * 32;

    const __half* srcs[4];
    int rbs[4];
    if (MODE == 1) {
        srcs[0] = A0; rbs[0] = bm;
        srcs[1] = B0; rbs[1] = bn;
        srcs[2] = B1; rbs[2] = bn;
        srcs[3] = nullptr; rbs[3] = 0;
    } else {
        srcs[0] = A0; rbs[0] = bm;
        srcs[1] = A1; rbs[1] = bm;
        srcs[2] = B0; rbs[2] = bn;
        srcs[3] = B1; rbs[3] = bn;
    }

    auto issue = [&](int stage, int kchunk) {
#pragma unroll
        for (int t = 0; t < NTILES; t++) {
#pragma unroll
            for (int u = 0; u < 4; u++) {
                const int v = tid + 256 * u;            // 0..1023
                const int row = v >> 3, c16 = v & 7;
                const uint32_t o = (uint32_t)(row * 128 + c16 * 16);
                cp16(sb + stage * STAGE_B + t * TILE_B + SWZ(o),
                     srcs[t] + (size_t)(rbs[t] + row) * K + kchunk * 64 + c16 * 8);
            }
        }
        asm volatile("cp.async.commit_group;");
    };

    float acc[4][4][4];
#pragma unroll
    for (int i = 0; i < 4; i++)
#pragma unroll
        for (int j = 0; j < 4; j++)
#pragma unroll
            for (int r = 0; r < 4; r++) acc[i][j][r] = 0.0f;

    const int nc = K / 64;
    issue(0, 0);
    issue(1, 1);

    const int arow   = lane & 15;
    const int achunk = lane >> 4;
    const int bsub   = lane >> 3;
    const int brow   = (lane & 7) + (bsub >> 1) * 8;
    const int bchunk = bsub & 1;

    for (int i = 0; i < nc; i++) {
        if (i < nc - 1) asm volatile("cp.async.wait_group 1;");
        else            asm volatile("cp.async.wait_group 0;");
        __syncthreads();

        if (i + 2 < nc) issue((i + 2) % 3, i + 2);

        const uint32_t base = sb + (i % 3) * STAGE_B;
        const int bt0 = (MODE == 1) ? 1 : 2;
#pragma unroll
        for (int s = 0; s < 4; s++) {                  // 4 x k16 per BK=64 chunk
            uint32_t a0[4][4], a1[4][4], b0r[4][2], b1r[4][2];
#pragma unroll
            for (int t = 0; t < 4; t++) {
                const uint32_t o =
                    (uint32_t)((wm + t * 16 + arow) * 128 + (s * 2 + achunk) * 16);
                ldm_x4(a0[t], base + SWZ(o));
                if (MODE != 1) ldm_x4(a1[t], base + TILE_B + SWZ(o));
            }
#pragma unroll
            for (int g = 0; g < 2; g++) {
                const uint32_t o =
                    (uint32_t)((wn + g * 16 + brow) * 128 + (s * 2 + bchunk) * 16);
                uint32_t r[4];
                ldm_x4(r, base + bt0 * TILE_B + SWZ(o));
                b0r[2 * g][0] = r[0]; b0r[2 * g][1] = r[1];
                b0r[2 * g + 1][0] = r[2]; b0r[2 * g + 1][1] = r[3];
                ldm_x4(r, base + (bt0 + 1) * TILE_B + SWZ(o));
                b1r[2 * g][0] = r[0]; b1r[2 * g][1] = r[1];
                b1r[2 * g + 1][0] = r[2]; b1r[2 * g + 1][1] = r[3];
            }
#pragma unroll
            for (int mt = 0; mt < 4; mt++)
#pragma unroll
                for (int nt = 0; nt < 4; nt++) {
                    mma_f16(acc[mt][nt], a0[mt], b0r[nt]);
                    mma_f16(acc[mt][nt], a0[mt], b1r[nt]);
                    if (MODE != 1) mma_f16(acc[mt][nt], a1[mt], b0r[nt]);
                }
        }
    }

    // ---- epilogue ----
    const int r0 = bm + wm + (lane >> 2);
    const int c0 = wn + (lane & 3) * 2;

    if (MODE == 2) {
        const int region = bn >> 10;                   // 0=Q, 1=K, 2=V
        const int cb = bn & 1023;
#pragma unroll
        for (int mt = 0; mt < 4; mt++)
#pragma unroll
            for (int nt = 0; nt < 4; nt++) {
                const int row = r0 + mt * 16;
                const int col = cb + c0 + nt * 8;
                const size_t i0 = (size_t)row * DD + col;
                const size_t i1 = (size_t)(row + 8) * DD + col;
                if (region == 0) {
                    split_store_f16(g_Qh, g_Ql, i0, acc[mt][nt][0], acc[mt][nt][1]);
                    split_store_f16(g_Qh, g_Ql, i1, acc[mt][nt][2], acc[mt][nt][3]);
                } else if (region == 1) {
                    split_store_f16(g_Kh, g_Kl, i0, acc[mt][nt][0], acc[mt][nt][1]);
                    split_store_f16(g_Kh, g_Kl, i1, acc[mt][nt][2], acc[mt][nt][3]);
                } else {
                    *reinterpret_cast<float2*>(g_V + i0) =
                        make_float2(acc[mt][nt][0], acc[mt][nt][1]);
                    *reinterpret_cast<float2*>(g_V + i1) =
                        make_float2(acc[mt][nt][2], acc[mt][nt][3]);
                }
            }
    } else {
#pragma unroll
        for (int mt = 0; mt < 4; mt++)
#pragma unroll
            for (int nt = 0; nt < 4; nt++) {
                const int row = r0 + mt * 16;
                const int col = bn + c0 + nt * 8;
                *reinterpret_cast<float2*>(C + (size_t)row * N + col) =
                    make_float2(acc[mt][nt][0] * alpha, acc[mt][nt][1] * alpha);
                *reinterpret_cast<float2*>(C + (size_t)(row + 8) * N + col) =
                    make_float2(acc[mt][nt][2] * alpha, acc[mt][nt][3] * alpha);
            }
    }
}

// ---------------------------------------------------------------------------
// fp32 -> (hi, lo) fp16 split, contiguous
// ---------------------------------------------------------------------------
__global__ __launch_bounds__(256)
void split_f16(const float* __restrict__ in, __half* __restrict__ hi,
               __half* __restrict__ lo, int n)
{
    const int idx = (blockIdx.x * 256 + threadIdx.x) * 2;
    if (idx < n) {
        const float2 v = *reinterpret_cast<const float2*>(in + idx);
        split_store_f16(hi, lo, idx, v.x, v.y);
    }
}

// ---------------------------------------------------------------------------
// fp32 [R,C] -> transposed (hi,lo) fp16 [C,R]
// ---------------------------------------------------------------------------
__global__ __launch_bounds__(256)
void tsplit_f16(const float* __restrict__ in,
                __half* __restrict__ oh, __half* __restrict__ ol, int R, int C)
{
    __shared__ float t[32][33];
    const int bx = blockIdx.x * 32, by = blockIdx.y * 32;
    const int tx = threadIdx.x & 31, ty = threadIdx.x >> 5;
#pragma unroll
    for (int j = 0; j < 32; j += 8)
        t[ty + j][tx] = in[(size_t)(by + ty + j) * C + bx + tx];
    __syncthreads();
#pragma unroll
    for (int j = 0; j < 32; j += 8) {
        const float v = t[tx][ty + j];
        const __half h = __float2half_rn(v);
        const size_t o = (size_t)(bx + ty + j) * R + by + tx;
        oh[o] = h;
        ol[o] = __float2half_rn(v - __half2float(h));
    }
}

// ---------------------------------------------------------------------------
// Row softmax over S[4096][4096] -> P fp16
// ---------------------------------------------------------------------------
__global__ __launch_bounds__(256)
void softmax_f16(const float* __restrict__ S, __half* __restrict__ Ph)
{
    const int row = blockIdx.x;
    const float* p = S + (size_t)row * NT;
    const int tid = threadIdx.x;
    const int base = tid * 16;

    float v[16];
#pragma unroll
    for (int q = 0; q < 4; q++) {
        const float4 x4 = *reinterpret_cast<const float4*>(p + base + q * 4);
        v[q * 4 + 0] = x4.x; v[q * 4 + 1] = x4.y; v[q * 4 + 2] = x4.z; v[q * 4 + 3] = x4.w;
    }

    __shared__ float red[256];
    float m = v[0];
#pragma unroll
    for (int q = 1; q < 16; q++) m = fmaxf(m, v[q]);
    red[tid] = m;
    __syncthreads();
#pragma unroll
    for (int s = 128; s > 0; s >>= 1) {
        if (tid < s) red[tid] = fmaxf(red[tid], red[tid + s]);
        __syncthreads();
    }
    m = red[0];
    __syncthreads();

    float sum = 0.0f;
#pragma unroll
    for (int q = 0; q < 16; q++) { v[q] = expf(v[q] - m); sum += v[q]; }
    red[tid] = sum;
    __syncthreads();
#pragma unroll
    for (int s = 128; s > 0; s >>= 1) {
        if (tid < s) red[tid] += red[tid + s];
        __syncthreads();
    }
    const float inv = 1.0f / red[0];

    __half* ph = Ph + (size_t)row * NT + base;
#pragma unroll
    for (int q = 0; q < 8; q++) {
        *reinterpret_cast<__half2*>(ph + 2 * q) =
            __floats2half2_rn(v[2 * q] * inv, v[2 * q + 1] * inv);
    }
}

// ---------------------------------------------------------------------------
// kernel_launch
// ---------------------------------------------------------------------------
extern "C" void kernel_launch(void* const* d_in, const int* in_sizes, int n_in,
                              void* d_out, int out_size)
{
    const float* x  = (const float*)d_in[0];
    const float* wq = (const float*)d_in[1];
    const float* wk = (const float*)d_in[2];
    const float* wv = (const float*)d_in[3];
    float* out = (float*)d_out;

    float *V, *S;
    __half *xh, *xl, *wh, *wl, *Qh, *Ql, *Kh, *Kl, *Vth, *Vtl, *Ph;
    cudaGetSymbolAddress((void**)&V, g_V);
    cudaGetSymbolAddress((void**)&S, g_S);
    cudaGetSymbolAddress((void**)&xh, g_xh);
    cudaGetSymbolAddress((void**)&xl, g_xl);
    cudaGetSymbolAddress((void**)&wh, g_wh);
    cudaGetSymbolAddress((void**)&wl, g_wl);
    cudaGetSymbolAddress((void**)&Qh, g_Qh);
    cudaGetSymbolAddress((void**)&Ql, g_Ql);
    cudaGetSymbolAddress((void**)&Kh, g_Kh);
    cudaGetSymbolAddress((void**)&Kl, g_Kl);
    cudaGetSymbolAddress((void**)&Vth, g_Vth);
    cudaGetSymbolAddress((void**)&Vtl, g_Vtl);
    cudaGetSymbolAddress((void**)&Ph, g_Ph);

    static bool attr_done = false;
    if (!attr_done) {
        cudaFuncSetAttribute(gemm_mma<0>, cudaFuncAttributeMaxDynamicSharedMemorySize,
                             3 * 4 * TILE_B);
        cudaFuncSetAttribute(gemm_mma<1>, cudaFuncAttributeMaxDynamicSharedMemorySize,
                             3 * 3 * TILE_B);
        cudaFuncSetAttribute(gemm_mma<2>, cudaFuncAttributeMaxDynamicSharedMemorySize,
                             3 * 4 * TILE_B);
        attr_done = true;
    }

    const size_t WW = (size_t)DD * DD;
    const dim3 blk(256);

    // 1) prep: split x (hi+lo fp16), transpose+split weights (cat [3072,1024] = W^T)
    split_f16<<<NT * DD / 512, blk>>>(x, xh, xl, NT * DD);
    {
        const dim3 g(DD / 32, DD / 32);
        tsplit_f16<<<g, blk>>>(wq, wh + 0 * WW, wl + 0 * WW, DD, DD);
        tsplit_f16<<<g, blk>>>(wk, wh + 1 * WW, wl + 1 * WW, DD, DD);
        tsplit_f16<<<g, blk>>>(wv, wh + 2 * WW, wl + 2 * WW, DD, DD);
    }

    // 2) fused projections (3-term everywhere; epi writes Q/K splits + V fp32)
    gemm_mma<2><<<dim3(3 * DD / 128, NT / 128), blk, 3 * 4 * TILE_B>>>(
        xh, xl, wh, wl, nullptr, NT, 3 * DD, DD, 1.0f);

    // 3) V^T fp16 split
    tsplit_f16<<<dim3(DD / 32, NT / 32), blk>>>(V, Vth, Vtl, NT, DD);

    // 4) scores: S = (Q @ K^T) / 32   (fp16 3-term)
    gemm_mma<0><<<dim3(NT / 128, NT / 128), blk, 3 * 4 * TILE_B>>>(
        Qh, Ql, Kh, Kl, S, NT, NT, DD, 1.0f / 32.0f);

    // 5) softmax -> P fp16
    softmax_f16<<<NT, blk>>>(S, Ph);

    // 6) out = P @ V   (fp16 2-term; B = V^T [1024, 4096])
    gemm_mma<1><<<dim3(DD / 128, NT / 128), blk, 3 * 3 * TILE_B>>>(
        Ph, nullptr, Vth, Vtl, out, NT, DD, NT, 1.0f);
}

// round 7
// speedup vs baseline: 3.8420x; 1.1308x over previous
#include <cuda_runtime.h>
#include <cuda_fp16.h>
#include <cstdint>

static constexpr int NT = 4096;   // tokens
static constexpr int DD = 1024;   // d_in == d_out

// ---------------- scratch (__device__ globals: allocation-free rule) --------
__device__ float g_V[(size_t)NT * DD];              // fp32 V from proj epilogue
__device__ float g_S[(size_t)NT * NT];              // fp32 scores

__device__ __half g_xh[(size_t)NT * DD], g_xl[(size_t)NT * DD];
__device__ __half g_wh[(size_t)3 * DD * DD], g_wl[(size_t)3 * DD * DD];   // cat W^T
__device__ __half g_Qh[(size_t)NT * DD], g_Ql[(size_t)NT * DD];
__device__ __half g_Kh[(size_t)NT * DD], g_Kl[(size_t)NT * DD];
__device__ __half g_Vth[(size_t)DD * NT];                                 // V^T fp16
__device__ __half g_Ph[(size_t)NT * NT];                                  // P fp16

// ---------------- helpers ---------------------------------------------------
__device__ __forceinline__ uint32_t smem_u32(const void* p) {
    uint32_t a;
    asm("{ .reg .u64 t; cvta.to.shared.u64 t, %1; cvt.u32.u64 %0, t; }"
        : "=r"(a) : "l"(p));
    return a;
}

// 128B-row swizzle: XOR 16B-chunk index (bits 4-6) with row%8 (bits 7-9)
#define SWZ(o) ((o) ^ ((((uint32_t)(o)) >> 3) & 0x70))

__device__ __forceinline__ void cp16(uint32_t saddr, const void* gaddr) {
    asm volatile("cp.async.cg.shared.global [%0], [%1], 16;"
                 :: "r"(saddr), "l"(gaddr));
}

__device__ __forceinline__ void ldm_x4(uint32_t* r, uint32_t addr) {
    asm volatile("ldmatrix.sync.aligned.m8n8.x4.shared.b16 {%0,%1,%2,%3}, [%4];"
                 : "=r"(r[0]), "=r"(r[1]), "=r"(r[2]), "=r"(r[3]) : "r"(addr));
}

__device__ __forceinline__ void mma_f16(float* c, const uint32_t* a, const uint32_t* b) {
    asm volatile(
        "mma.sync.aligned.m16n8k16.row.col.f32.f16.f16.f32 "
        "{%0,%1,%2,%3}, {%4,%5,%6,%7}, {%8,%9}, {%0,%1,%2,%3};"
        : "+f"(c[0]), "+f"(c[1]), "+f"(c[2]), "+f"(c[3])
        : "r"(a[0]), "r"(a[1]), "r"(a[2]), "r"(a[3]), "r"(b[0]), "r"(b[1]));
}

__device__ __forceinline__ void split_store_f16(
    __half* H, __half* L, size_t idx, float a, float b)
{
    const __half h0 = __float2half_rn(a);
    const __half h1 = __float2half_rn(b);
    const __half l0 = __float2half_rn(a - __half2float(h0));
    const __half l1 = __float2half_rn(b - __half2float(h1));
    *reinterpret_cast<__half2*>(H + idx) = __halves2half2(h0, h1);
    *reinterpret_cast<__half2*>(L + idx) = __halves2half2(l0, l1);
}

// ---------------------------------------------------------------------------
// Warp-MMA split-fp16 GEMM, BK=64, 3-stage cp.async pipeline.
//   MODE 0 (scores): C = alpha*(A@B^T); 3 terms A0B0+A0B1+A1B0; tiles A0,A1,B0,B1.
//   MODE 1 (PV):     C = A@B^T; 1 term A0B0; tiles A0,B0.
//   MODE 2 (proj):   Q/K region (bn<2048): 3 terms; V region: 2 terms (A0B0+A0B1,
//                    skips A1 loads). Epilogue: Qh/Ql, Kh/Kl splits + g_V fp32.
// BM=BN=128, BK=64, 256 threads, 2(m)x4(n) warps, 64x32 warp tile.
// ---------------------------------------------------------------------------
static constexpr int TILE_B = 128 * 128;   // 16 KB (128 rows x 64 fp16)

template <int MODE>
__global__ __launch_bounds__(256, 1)
void gemm_mma(const __half* __restrict__ A0, const __half* __restrict__ A1,
              const __half* __restrict__ B0, const __half* __restrict__ B1,
              float* __restrict__ C, int M, int N, int K, float alpha)
{
    constexpr int NTILES  = (MODE == 1) ? 2 : 4;
    constexpr int STAGE_B = NTILES * TILE_B;

    extern __shared__ char smem[];
    const uint32_t sb = smem_u32(smem);
    const int tid  = threadIdx.x;
    const int wid  = tid >> 5;
    const int lane = tid & 31;
    const int bm = blockIdx.y * 128;
    const int bn = blockIdx.x * 128;
    const int wm = (wid >> 2) * 64;
    const int wn = (wid & 3) * 32;

    // 3rd term (A1*B0) only where needed: scores always; proj only for Q/K region
    const bool t3 = (MODE == 0) || (MODE == 2 && bn < 2048);

    const __half* srcs[4];
    int rbs[4];
    if (MODE == 1) {
        srcs[0] = A0; rbs[0] = bm;
        srcs[1] = B0; rbs[1] = bn;
        srcs[2] = nullptr; rbs[2] = 0;
        srcs[3] = nullptr; rbs[3] = 0;
    } else {
        srcs[0] = A0; rbs[0] = bm;
        srcs[1] = A1; rbs[1] = bm;
        srcs[2] = B0; rbs[2] = bn;
        srcs[3] = B1; rbs[3] = bn;
    }

    auto issue = [&](int stage, int kchunk) {
#pragma unroll
        for (int t = 0; t < NTILES; t++) {
            if (MODE == 2 && t == 1 && !t3) continue;   // V region: skip xl tile
#pragma unroll
            for (int u = 0; u < 4; u++) {
                const int v = tid + 256 * u;            // 0..1023
                const int row = v >> 3, c16 = v & 7;
                const uint32_t o = (uint32_t)(row * 128 + c16 * 16);
                cp16(sb + stage * STAGE_B + t * TILE_B + SWZ(o),
                     srcs[t] + (size_t)(rbs[t] + row) * K + kchunk * 64 + c16 * 8);
            }
        }
        asm volatile("cp.async.commit_group;");
    };

    float acc[4][4][4];
#pragma unroll
    for (int i = 0; i < 4; i++)
#pragma unroll
        for (int j = 0; j < 4; j++)
#pragma unroll
            for (int r = 0; r < 4; r++) acc[i][j][r] = 0.0f;

    const int nc = K / 64;
    issue(0, 0);
    issue(1, 1);

    const int arow   = lane & 15;
    const int achunk = lane >> 4;
    const int bsub   = lane >> 3;
    const int brow   = (lane & 7) + (bsub >> 1) * 8;
    const int bchunk = bsub & 1;

    for (int i = 0; i < nc; i++) {
        if (i < nc - 1) asm volatile("cp.async.wait_group 1;");
        else            asm volatile("cp.async.wait_group 0;");
        __syncthreads();

        if (i + 2 < nc) issue((i + 2) % 3, i + 2);

        const uint32_t base = sb + (i % 3) * STAGE_B;
        const int bt0 = (MODE == 1) ? 1 : 2;
#pragma unroll
        for (int s = 0; s < 4; s++) {                  // 4 x k16 per BK=64 chunk
            uint32_t a0[4][4], a1[4][4], b0r[4][2], b1r[4][2];
#pragma unroll
            for (int t = 0; t < 4; t++) {
                const uint32_t o =
                    (uint32_t)((wm + t * 16 + arow) * 128 + (s * 2 + achunk) * 16);
                ldm_x4(a0[t], base + SWZ(o));
                if (MODE != 1) {
                    if (t3) ldm_x4(a1[t], base + TILE_B + SWZ(o));
                }
            }
#pragma unroll
            for (int g = 0; g < 2; g++) {
                const uint32_t o =
                    (uint32_t)((wn + g * 16 + brow) * 128 + (s * 2 + bchunk) * 16);
                uint32_t r[4];
                ldm_x4(r, base + bt0 * TILE_B + SWZ(o));
                b0r[2 * g][0] = r[0]; b0r[2 * g][1] = r[1];
                b0r[2 * g + 1][0] = r[2]; b0r[2 * g + 1][1] = r[3];
                if (MODE != 1) {
                    ldm_x4(r, base + (bt0 + 1) * TILE_B + SWZ(o));
                    b1r[2 * g][0] = r[0]; b1r[2 * g][1] = r[1];
                    b1r[2 * g + 1][0] = r[2]; b1r[2 * g + 1][1] = r[3];
                }
            }
#pragma unroll
            for (int mt = 0; mt < 4; mt++)
#pragma unroll
                for (int nt = 0; nt < 4; nt++) {
                    mma_f16(acc[mt][nt], a0[mt], b0r[nt]);
                    if (MODE != 1) {
                        mma_f16(acc[mt][nt], a0[mt], b1r[nt]);
                        if (t3) mma_f16(acc[mt][nt], a1[mt], b0r[nt]);
                    }
                }
        }
    }

    // ---- epilogue ----
    const int r0 = bm + wm + (lane >> 2);
    const int c0 = wn + (lane & 3) * 2;

    if (MODE == 2) {
        const int region = bn >> 10;                   // 0=Q, 1=K, 2=V
        const int cb = bn & 1023;
#pragma unroll
        for (int mt = 0; mt < 4; mt++)
#pragma unroll
            for (int nt = 0; nt < 4; nt++) {
                const int row = r0 + mt * 16;
                const int col = cb + c0 + nt * 8;
                const size_t i0 = (size_t)row * DD + col;
                const size_t i1 = (size_t)(row + 8) * DD + col;
                if (region == 0) {
                    split_store_f16(g_Qh, g_Ql, i0, acc[mt][nt][0], acc[mt][nt][1]);
                    split_store_f16(g_Qh, g_Ql, i1, acc[mt][nt][2], acc[mt][nt][3]);
                } else if (region == 1) {
                    split_store_f16(g_Kh, g_Kl, i0, acc[mt][nt][0], acc[mt][nt][1]);
                    split_store_f16(g_Kh, g_Kl, i1, acc[mt][nt][2], acc[mt][nt][3]);
                } else {
                    *reinterpret_cast<float2*>(g_V + i0) =
                        make_float2(acc[mt][nt][0], acc[mt][nt][1]);
                    *reinterpret_cast<float2*>(g_V + i1) =
                        make_float2(acc[mt][nt][2], acc[mt][nt][3]);
                }
            }
    } else {
#pragma unroll
        for (int mt = 0; mt < 4; mt++)
#pragma unroll
            for (int nt = 0; nt < 4; nt++) {
                const int row = r0 + mt * 16;
                const int col = bn + c0 + nt * 8;
                *reinterpret_cast<float2*>(C + (size_t)row * N + col) =
                    make_float2(acc[mt][nt][0] * alpha, acc[mt][nt][1] * alpha);
                *reinterpret_cast<float2*>(C + (size_t)(row + 8) * N + col) =
                    make_float2(acc[mt][nt][2] * alpha, acc[mt][nt][3] * alpha);
            }
    }
}

// ---------------------------------------------------------------------------
// fp32 -> (hi, lo) fp16 split, contiguous
// ---------------------------------------------------------------------------
__global__ __launch_bounds__(256)
void split_f16(const float* __restrict__ in, __half* __restrict__ hi,
               __half* __restrict__ lo, int n)
{
    const int idx = (blockIdx.x * 256 + threadIdx.x) * 2;
    if (idx < n) {
        const float2 v = *reinterpret_cast<const float2*>(in + idx);
        split_store_f16(hi, lo, idx, v.x, v.y);
    }
}

// ---------------------------------------------------------------------------
// fp32 [R,C] -> transposed (hi,lo) fp16 [C,R]   (weights)
// ---------------------------------------------------------------------------
__global__ __launch_bounds__(256)
void tsplit_f16(const float* __restrict__ in,
                __half* __restrict__ oh, __half* __restrict__ ol, int R, int C)
{
    __shared__ float t[32][33];
    const int bx = blockIdx.x * 32, by = blockIdx.y * 32;
    const int tx = threadIdx.x & 31, ty = threadIdx.x >> 5;
#pragma unroll
    for (int j = 0; j < 32; j += 8)
        t[ty + j][tx] = in[(size_t)(by + ty + j) * C + bx + tx];
    __syncthreads();
#pragma unroll
    for (int j = 0; j < 32; j += 8) {
        const float v = t[tx][ty + j];
        const __half h = __float2half_rn(v);
        const size_t o = (size_t)(bx + ty + j) * R + by + tx;
        oh[o] = h;
        ol[o] = __float2half_rn(v - __half2float(h));
    }
}

// ---------------------------------------------------------------------------
// fp32 [R,C] -> transposed fp16 [C,R], hi only   (V^T)
// ---------------------------------------------------------------------------
__global__ __launch_bounds__(256)
void t_h16(const float* __restrict__ in, __half* __restrict__ oh, int R, int C)
{
    __shared__ float t[32][33];
    const int bx = blockIdx.x * 32, by = blockIdx.y * 32;
    const int tx = threadIdx.x & 31, ty = threadIdx.x >> 5;
#pragma unroll
    for (int j = 0; j < 32; j += 8)
        t[ty + j][tx] = in[(size_t)(by + ty + j) * C + bx + tx];
    __syncthreads();
#pragma unroll
    for (int j = 0; j < 32; j += 8) {
        const float v = t[tx][ty + j];
        oh[(size_t)(bx + ty + j) * R + by + tx] = __float2half_rn(v);
    }
}

// ---------------------------------------------------------------------------
// Row softmax over S[4096][4096] -> P fp16
// ---------------------------------------------------------------------------
__global__ __launch_bounds__(256)
void softmax_f16(const float* __restrict__ S, __half* __restrict__ Ph)
{
    const int row = blockIdx.x;
    const float* p = S + (size_t)row * NT;
    const int tid = threadIdx.x;
    const int base = tid * 16;

    float v[16];
#pragma unroll
    for (int q = 0; q < 4; q++) {
        const float4 x4 = *reinterpret_cast<const float4*>(p + base + q * 4);
        v[q * 4 + 0] = x4.x; v[q * 4 + 1] = x4.y; v[q * 4 + 2] = x4.z; v[q * 4 + 3] = x4.w;
    }

    __shared__ float red[256];
    float m = v[0];
#pragma unroll
    for (int q = 1; q < 16; q++) m = fmaxf(m, v[q]);
    red[tid] = m;
    __syncthreads();
#pragma unroll
    for (int s = 128; s > 0; s >>= 1) {
        if (tid < s) red[tid] = fmaxf(red[tid], red[tid + s]);
        __syncthreads();
    }
    m = red[0];
    __syncthreads();

    float sum = 0.0f;
#pragma unroll
    for (int q = 0; q < 16; q++) { v[q] = expf(v[q] - m); sum += v[q]; }
    red[tid] = sum;
    __syncthreads();
#pragma unroll
    for (int s = 128; s > 0; s >>= 1) {
        if (tid < s) red[tid] += red[tid + s];
        __syncthreads();
    }
    const float inv = 1.0f / red[0];

    __half* ph = Ph + (size_t)row * NT + base;
#pragma unroll
    for (int q = 0; q < 8; q++) {
        *reinterpret_cast<__half2*>(ph + 2 * q) =
            __floats2half2_rn(v[2 * q] * inv, v[2 * q + 1] * inv);
    }
}

// ---------------------------------------------------------------------------
// kernel_launch
// ---------------------------------------------------------------------------
extern "C" void kernel_launch(void* const* d_in, const int* in_sizes, int n_in,
                              void* d_out, int out_size)
{
    const float* x  = (const float*)d_in[0];
    const float* wq = (const float*)d_in[1];
    const float* wk = (const float*)d_in[2];
    const float* wv = (const float*)d_in[3];
    float* out = (float*)d_out;

    float *V, *S;
    __half *xh, *xl, *wh, *wl, *Qh, *Ql, *Kh, *Kl, *Vth, *Ph;
    cudaGetSymbolAddress((void**)&V, g_V);
    cudaGetSymbolAddress((void**)&S, g_S);
    cudaGetSymbolAddress((void**)&xh, g_xh);
    cudaGetSymbolAddress((void**)&xl, g_xl);
    cudaGetSymbolAddress((void**)&wh, g_wh);
    cudaGetSymbolAddress((void**)&wl, g_wl);
    cudaGetSymbolAddress((void**)&Qh, g_Qh);
    cudaGetSymbolAddress((void**)&Ql, g_Ql);
    cudaGetSymbolAddress((void**)&Kh, g_Kh);
    cudaGetSymbolAddress((void**)&Kl, g_Kl);
    cudaGetSymbolAddress((void**)&Vth, g_Vth);
    cudaGetSymbolAddress((void**)&Ph, g_Ph);

    static bool attr_done = false;
    if (!attr_done) {
        cudaFuncSetAttribute(gemm_mma<0>, cudaFuncAttributeMaxDynamicSharedMemorySize,
                             3 * 4 * TILE_B);
        cudaFuncSetAttribute(gemm_mma<1>, cudaFuncAttributeMaxDynamicSharedMemorySize,
                             3 * 2 * TILE_B);
        cudaFuncSetAttribute(gemm_mma<2>, cudaFuncAttributeMaxDynamicSharedMemorySize,
                             3 * 4 * TILE_B);
        attr_done = true;
    }

    const size_t WW = (size_t)DD * DD;
    const dim3 blk(256);

    // 1) prep: split x (hi+lo fp16), transpose+split weights (cat [3072,1024] = W^T)
    split_f16<<<NT * DD / 512, blk>>>(x, xh, xl, NT * DD);
    {
        const dim3 g(DD / 32, DD / 32);
        tsplit_f16<<<g, blk>>>(wq, wh + 0 * WW, wl + 0 * WW, DD, DD);
        tsplit_f16<<<g, blk>>>(wk, wh + 1 * WW, wl + 1 * WW, DD, DD);
        tsplit_f16<<<g, blk>>>(wv, wh + 2 * WW, wl + 2 * WW, DD, DD);
    }

    // 2) fused projections (Q/K: 3-term; V: 2-term; epi writes Q/K splits + V fp32)
    gemm_mma<2><<<dim3(3 * DD / 128, NT / 128), blk, 3 * 4 * TILE_B>>>(
        xh, xl, wh, wl, nullptr, NT, 3 * DD, DD, 1.0f);

    // 3) V^T fp16 (hi only)
    t_h16<<<dim3(DD / 32, NT / 32), blk>>>(V, Vth, NT, DD);

    // 4) scores: S = (Q @ K^T) / 32   (fp16 3-term)
    gemm_mma<0><<<dim3(NT / 128, NT / 128), blk, 3 * 4 * TILE_B>>>(
        Qh, Ql, Kh, Kl, S, NT, NT, DD, 1.0f / 32.0f);

    // 5) softmax -> P fp16
    softmax_f16<<<NT, blk>>>(S, Ph);

    // 6) out = P @ V   (fp16 1-term; B = V^T [1024, 4096])
    gemm_mma<1><<<dim3(DD / 128, NT / 128), blk, 3 * 2 * TILE_B>>>(
        Ph, nullptr, Vth, nullptr, out, NT, DD, NT, 1.0f);
}

// round 9
// speedup vs baseline: 4.0281x; 1.0484x over previous
#include <cuda_runtime.h>
#include <cuda_fp16.h>
#include <cstdint>

static constexpr int NT = 4096;   // tokens
static constexpr int DD = 1024;   // d_in == d_out
static constexpr size_t WW = (size_t)DD * DD;

// ---------------- scratch (__device__ globals: allocation-free rule) --------
__device__ float g_V[(size_t)NT * DD];              // fp32 V from prep epilogue
__device__ float g_S[(size_t)NT * NT];              // fp32 scores

__device__ __half g_xh[(size_t)NT * DD], g_xl[(size_t)NT * DD];
// region 0: Wq (untransposed) | region 1: Wk (untransposed) | region 2: Wv^T
__device__ __half g_wh[(size_t)3 * DD * DD], g_wl[(size_t)3 * DD * DD];
__device__ __half g_Th[(size_t)NT * DD], g_Tl[(size_t)NT * DD];           // T = x@M
__device__ __half g_MTh[(size_t)DD * DD], g_MTl[(size_t)DD * DD];         // M^T
__device__ __half g_Vth[(size_t)DD * NT];                                 // V^T fp16
__device__ __half g_Ph[(size_t)NT * NT];                                  // P fp16

// ---------------- helpers ---------------------------------------------------
__device__ __forceinline__ uint32_t smem_u32(const void* p) {
    uint32_t a;
    asm("{ .reg .u64 t; cvta.to.shared.u64 t, %1; cvt.u32.u64 %0, t; }"
        : "=r"(a) : "l"(p));
    return a;
}

// 128B-row swizzle: XOR 16B-chunk index (bits 4-6) with row%8 (bits 7-9)
#define SWZ(o) ((o) ^ ((((uint32_t)(o)) >> 3) & 0x70))

__device__ __forceinline__ void cp16(uint32_t saddr, const void* gaddr) {
    asm volatile("cp.async.cg.shared.global [%0], [%1], 16;"
                 :: "r"(saddr), "l"(gaddr));
}

__device__ __forceinline__ void ldm_x4(uint32_t* r, uint32_t addr) {
    asm volatile("ldmatrix.sync.aligned.m8n8.x4.shared.b16 {%0,%1,%2,%3}, [%4];"
                 : "=r"(r[0]), "=r"(r[1]), "=r"(r[2]), "=r"(r[3]) : "r"(addr));
}

__device__ __forceinline__ void mma_f16(float* c, const uint32_t* a, const uint32_t* b) {
    asm volatile(
        "mma.sync.aligned.m16n8k16.row.col.f32.f16.f16.f32 "
        "{%0,%1,%2,%3}, {%4,%5,%6,%7}, {%8,%9}, {%0,%1,%2,%3};"
        : "+f"(c[0]), "+f"(c[1]), "+f"(c[2]), "+f"(c[3])
        : "r"(a[0]), "r"(a[1]), "r"(a[2]), "r"(a[3]), "r"(b[0]), "r"(b[1]));
}

__device__ __forceinline__ void split_store_f16(
    __half* H, __half* L, size_t idx, float a, float b)
{
    const __half h0 = __float2half_rn(a);
    const __half h1 = __float2half_rn(b);
    const __half l0 = __float2half_rn(a - __half2float(h0));
    const __half l1 = __float2half_rn(b - __half2float(h1));
    *reinterpret_cast<__half2*>(H + idx) = __halves2half2(h0, h1);
    *reinterpret_cast<__half2*>(L + idx) = __halves2half2(l0, l1);
}

// ---------------------------------------------------------------------------
// Warp-MMA split-fp16 GEMM, BK=64, 3-stage cp.async pipeline.
//  MODE 0 (scores): C = alpha*(A@B^T); 3 terms; tiles A0,A1,B0,B1; fp32 C.
//  MODE 1 (PV):     C = A@B^T; 1 term; tiles A0,B0; fp32 C.
//  MODE 2 (prep, fused grid):
//     by <  32: V = x @ Wv  (2 terms: xh*(WvT)h + xh*(WvT)l) -> g_V fp32
//     by >= 32: M^T = Wk @ Wq^T (3 terms; A=Wk splits, B=Wq splits, both
//               UNtransposed row-major [1024, K=1024]) -> g_MTh/g_MTl split
//  MODE 3 (T):      T = x @ M (3 terms; A=xh/xl, B=MTh/MTl) -> g_Th/g_Tl split
// BM=BN=128, BK=64, 256 threads, 2(m)x4(n) warps, 64x32 warp tile.
// ---------------------------------------------------------------------------
static constexpr int TILE_B = 128 * 128;   // 16 KB (128 rows x 64 fp16)

template <int MODE>
__global__ __launch_bounds__(256, 1)
void gemm_mma(const __half* __restrict__ A0, const __half* __restrict__ A1,
              const __half* __restrict__ B0, const __half* __restrict__ B1,
              float* __restrict__ C, int M, int N, int K, float alpha)
{
    constexpr int NTILES  = (MODE == 1) ? 2 : 4;
    constexpr int STAGE_B = NTILES * TILE_B;

    extern __shared__ char smem[];
    const uint32_t sb = smem_u32(smem);
    const int tid  = threadIdx.x;
    const int wid  = tid >> 5;
    const int lane = tid & 31;

    const bool isM = (MODE == 2) && (blockIdx.y >= 32);   // M^T region of prep
    const int bm = (MODE == 2 && isM) ? (blockIdx.y - 32) * 128 : blockIdx.y * 128;
    const int bn = blockIdx.x * 128;
    const int wm = (wid >> 2) * 64;
    const int wn = (wid & 3) * 32;

    // third term (A1*B0) usage
    const bool t3 = (MODE == 0) || (MODE == 3) || (MODE == 2 && isM);

    const __half* srcs[4];
    int rbs[4];
    if (MODE == 1) {
        srcs[0] = A0; rbs[0] = bm;
        srcs[1] = B0; rbs[1] = bn;
        srcs[2] = nullptr; rbs[2] = 0;
        srcs[3] = nullptr; rbs[3] = 0;
    } else if (MODE == 2) {
        if (isM) {      // A = Wk (untransposed) splits, B = Wq (untransposed) splits
            srcs[0] = g_wh + WW; srcs[1] = g_wl + WW;    // Wk hi/lo
            srcs[2] = g_wh;      srcs[3] = g_wl;         // Wq hi/lo
        } else {        // A = xh (2-term), B = Wv^T splits
            srcs[0] = g_xh;          srcs[1] = nullptr;
            srcs[2] = g_wh + 2 * WW; srcs[3] = g_wl + 2 * WW;
        }
        rbs[0] = bm; rbs[1] = bm; rbs[2] = bn; rbs[3] = bn;
    } else {
        srcs[0] = A0; rbs[0] = bm;
        srcs[1] = A1; rbs[1] = bm;
        srcs[2] = B0; rbs[2] = bn;
        srcs[3] = B1; rbs[3] = bn;
    }

    auto issue = [&](int stage, int kchunk) {
#pragma unroll
        for (int t = 0; t < NTILES; t++) {
            if (MODE == 2 && t == 1 && !t3) continue;   // V region: skip A1 tile
#pragma unroll
            for (int u = 0; u < 4; u++) {
                const int v = tid + 256 * u;            // 0..1023
                const int row = v >> 3, c16 = v & 7;
                const uint32_t o = (uint32_t)(row * 128 + c16 * 16);
                cp16(sb + stage * STAGE_B + t * TILE_B + SWZ(o),
                     srcs[t] + (size_t)(rbs[t] + row) * K + kchunk * 64 + c16 * 8);
            }
        }
        asm volatile("cp.async.commit_group;");
    };

    float acc[4][4][4];
#pragma unroll
    for (int i = 0; i < 4; i++)
#pragma unroll
        for (int j = 0; j < 4; j++)
#pragma unroll
            for (int r = 0; r < 4; r++) acc[i][j][r] = 0.0f;

    const int nc = K / 64;
    issue(0, 0);
    issue(1, 1);

    const int arow   = lane & 15;
    const int achunk = lane >> 4;
    const int bsub   = lane >> 3;
    const int brow   = (lane & 7) + (bsub >> 1) * 8;
    const int bchunk = bsub & 1;

    for (int i = 0; i < nc; i++) {
        if (i < nc - 1) asm volatile("cp.async.wait_group 1;");
        else            asm volatile("cp.async.wait_group 0;");
        __syncthreads();

        if (i + 2 < nc) issue((i + 2) % 3, i + 2);

        const uint32_t base = sb + (i % 3) * STAGE_B;
        const int bt0 = (MODE == 1) ? 1 : 2;
#pragma unroll
        for (int s = 0; s < 4; s++) {                  // 4 x k16 per BK=64 chunk
            uint32_t a0[4][4], a1[4][4], b0r[4][2], b1r[4][2];
#pragma unroll
            for (int t = 0; t < 4; t++) {
                const uint32_t o =
                    (uint32_t)((wm + t * 16 + arow) * 128 + (s * 2 + achunk) * 16);
                ldm_x4(a0[t], base + SWZ(o));
                if (MODE != 1) {
                    if (t3) ldm_x4(a1[t], base + TILE_B + SWZ(o));
                }
            }
#pragma unroll
            for (int g = 0; g < 2; g++) {
                const uint32_t o =
                    (uint32_t)((wn + g * 16 + brow) * 128 + (s * 2 + bchunk) * 16);
                uint32_t r[4];
                ldm_x4(r, base + bt0 * TILE_B + SWZ(o));
                b0r[2 * g][0] = r[0]; b0r[2 * g][1] = r[1];
                b0r[2 * g + 1][0] = r[2]; b0r[2 * g + 1][1] = r[3];
                if (MODE != 1) {
                    ldm_x4(r, base + (bt0 + 1) * TILE_B + SWZ(o));
                    b1r[2 * g][0] = r[0]; b1r[2 * g][1] = r[1];
                    b1r[2 * g + 1][0] = r[2]; b1r[2 * g + 1][1] = r[3];
                }
            }
#pragma unroll
            for (int mt = 0; mt < 4; mt++)
#pragma unroll
                for (int nt = 0; nt < 4; nt++) {
                    mma_f16(acc[mt][nt], a0[mt], b0r[nt]);
                    if (MODE != 1) {
                        mma_f16(acc[mt][nt], a0[mt], b1r[nt]);
                        if (t3) mma_f16(acc[mt][nt], a1[mt], b0r[nt]);
                    }
                }
        }
    }

    // ---- epilogue ----
    const int r0 = bm + wm + (lane >> 2);
    const int c0 = wn + (lane & 3) * 2;

    if (MODE == 2) {
#pragma unroll
        for (int mt = 0; mt < 4; mt++)
#pragma unroll
            for (int nt = 0; nt < 4; nt++) {
                const int row = r0 + mt * 16;
                const int col = bn + c0 + nt * 8;
                const size_t i0 = (size_t)row * DD + col;
                const size_t i1 = (size_t)(row + 8) * DD + col;
                if (isM) {
                    split_store_f16(g_MTh, g_MTl, i0, acc[mt][nt][0], acc[mt][nt][1]);
                    split_store_f16(g_MTh, g_MTl, i1, acc[mt][nt][2], acc[mt][nt][3]);
                } else {
                    *reinterpret_cast<float2*>(g_V + i0) =
                        make_float2(acc[mt][nt][0], acc[mt][nt][1]);
                    *reinterpret_cast<float2*>(g_V + i1) =
                        make_float2(acc[mt][nt][2], acc[mt][nt][3]);
                }
            }
    } else if (MODE == 3) {
#pragma unroll
        for (int mt = 0; mt < 4; mt++)
#pragma unroll
            for (int nt = 0; nt < 4; nt++) {
                const int row = r0 + mt * 16;
                const int col = bn + c0 + nt * 8;
                split_store_f16(g_Th, g_Tl, (size_t)row * DD + col,
                                acc[mt][nt][0], acc[mt][nt][1]);
                split_store_f16(g_Th, g_Tl, (size_t)(row + 8) * DD + col,
                                acc[mt][nt][2], acc[mt][nt][3]);
            }
    } else {
#pragma unroll
        for (int mt = 0; mt < 4; mt++)
#pragma unroll
            for (int nt = 0; nt < 4; nt++) {
                const int row = r0 + mt * 16;
                const int col = bn + c0 + nt * 8;
                *reinterpret_cast<float2*>(C + (size_t)row * N + col) =
                    make_float2(acc[mt][nt][0] * alpha, acc[mt][nt][1] * alpha);
                *reinterpret_cast<float2*>(C + (size_t)(row + 8) * N + col) =
                    make_float2(acc[mt][nt][2] * alpha, acc[mt][nt][3] * alpha);
            }
    }
}

// ---------------------------------------------------------------------------
// fp32 -> (hi, lo) fp16 split, contiguous (layout-preserving)
// ---------------------------------------------------------------------------
__global__ __launch_bounds__(256)
void split_f16(const float* __restrict__ in, __half* __restrict__ hi,
               __half* __restrict__ lo, int n)
{
    const int idx = (blockIdx.x * 256 + threadIdx.x) * 2;
    if (idx < n) {
        const float2 v = *reinterpret_cast<const float2*>(in + idx);
        split_store_f16(hi, lo, idx, v.x, v.y);
    }
}

// ---------------------------------------------------------------------------
// fp32 [R,C] -> transposed (hi,lo) fp16 [C,R]   (Wv -> Wv^T)
// ---------------------------------------------------------------------------
__global__ __launch_bounds__(256)
void tsplit_f16(const float* __restrict__ in,
                __half* __restrict__ oh, __half* __restrict__ ol, int R, int C)
{
    __shared__ float t[32][33];
    const int bx = blockIdx.x * 32, by = blockIdx.y * 32;
    const int tx = threadIdx.x & 31, ty = threadIdx.x >> 5;
#pragma unroll
    for (int j = 0; j < 32; j += 8)
        t[ty + j][tx] = in[(size_t)(by + ty + j) * C + bx + tx];
    __syncthreads();
#pragma unroll
    for (int j = 0; j < 32; j += 8) {
        const float v = t[tx][ty + j];
        const __half h = __float2half_rn(v);
        const size_t o = (size_t)(bx + ty + j) * R + by + tx;
        oh[o] = h;
        ol[o] = __float2half_rn(v - __half2float(h));
    }
}

// ---------------------------------------------------------------------------
// fp32 [R,C] -> transposed fp16 [C,R], hi only   (V -> V^T)
// ---------------------------------------------------------------------------
__global__ __launch_bounds__(256)
void t_h16(const float* __restrict__ in, __half* __restrict__ oh, int R, int C)
{
    __shared__ float t[32][33];
    const int bx = blockIdx.x * 32, by = blockIdx.y * 32;
    const int tx = threadIdx.x & 31, ty = threadIdx.x >> 5;
#pragma unroll
    for (int j = 0; j < 32; j += 8)
        t[ty + j][tx] = in[(size_t)(by + ty + j) * C + bx + tx];
    __syncthreads();
#pragma unroll
    for (int j = 0; j < 32; j += 8) {
        const float v = t[tx][ty + j];
        oh[(size_t)(bx + ty + j) * R + by + tx] = __float2half_rn(v);
    }
}

// ---------------------------------------------------------------------------
// Row softmax over S[4096][4096] -> P fp16
// ---------------------------------------------------------------------------
__global__ __launch_bounds__(256)
void softmax_f16(const float* __restrict__ S, __half* __restrict__ Ph)
{
    const int row = blockIdx.x;
    const float* p = S + (size_t)row * NT;
    const int tid = threadIdx.x;
    const int base = tid * 16;

    float v[16];
#pragma unroll
    for (int q = 0; q < 4; q++) {
        const float4 x4 = *reinterpret_cast<const float4*>(p + base + q * 4);
        v[q * 4 + 0] = x4.x; v[q * 4 + 1] = x4.y; v[q * 4 + 2] = x4.z; v[q * 4 + 3] = x4.w;
    }

    __shared__ float red[256];
    float m = v[0];
#pragma unroll
    for (int q = 1; q < 16; q++) m = fmaxf(m, v[q]);
    red[tid] = m;
    __syncthreads();
#pragma unroll
    for (int s = 128; s > 0; s >>= 1) {
        if (tid < s) red[tid] = fmaxf(red[tid], red[tid + s]);
        __syncthreads();
    }
    m = red[0];
    __syncthreads();

    float sum = 0.0f;
#pragma unroll
    for (int q = 0; q < 16; q++) { v[q] = expf(v[q] - m); sum += v[q]; }
    red[tid] = sum;
    __syncthreads();
#pragma unroll
    for (int s = 128; s > 0; s >>= 1) {
        if (tid < s) red[tid] += red[tid + s];
        __syncthreads();
    }
    const float inv = 1.0f / red[0];

    __half* ph = Ph + (size_t)row * NT + base;
#pragma unroll
    for (int q = 0; q < 8; q++) {
        *reinterpret_cast<__half2*>(ph + 2 * q) =
            __floats2half2_rn(v[2 * q] * inv, v[2 * q + 1] * inv);
    }
}

// ---------------------------------------------------------------------------
// kernel_launch
// ---------------------------------------------------------------------------
extern "C" void kernel_launch(void* const* d_in, const int* in_sizes, int n_in,
                              void* d_out, int out_size)
{
    const float* x  = (const float*)d_in[0];
    const float* wq = (const float*)d_in[1];
    const float* wk = (const float*)d_in[2];
    const float* wv = (const float*)d_in[3];
    float* out = (float*)d_out;

    float *V, *S;
    __half *xh, *xl, *wh, *wl, *Th, *Tl, *MTh, *MTl, *Vth, *Ph;
    cudaGetSymbolAddress((void**)&V, g_V);
    cudaGetSymbolAddress((void**)&S, g_S);
    cudaGetSymbolAddress((void**)&xh, g_xh);
    cudaGetSymbolAddress((void**)&xl, g_xl);
    cudaGetSymbolAddress((void**)&wh, g_wh);
    cudaGetSymbolAddress((void**)&wl, g_wl);
    cudaGetSymbolAddress((void**)&Th, g_Th);
    cudaGetSymbolAddress((void**)&Tl, g_Tl);
    cudaGetSymbolAddress((void**)&MTh, g_MTh);
    cudaGetSymbolAddress((void**)&MTl, g_MTl);
    cudaGetSymbolAddress((void**)&Vth, g_Vth);
    cudaGetSymbolAddress((void**)&Ph, g_Ph);

    static bool attr_done = false;
    if (!attr_done) {
        cudaFuncSetAttribute(gemm_mma<0>, cudaFuncAttributeMaxDynamicSharedMemorySize,
                             3 * 4 * TILE_B);
        cudaFuncSetAttribute(gemm_mma<1>, cudaFuncAttributeMaxDynamicSharedMemorySize,
                             3 * 2 * TILE_B);
        cudaFuncSetAttribute(gemm_mma<2>, cudaFuncAttributeMaxDynamicSharedMemorySize,
                             3 * 4 * TILE_B);
        cudaFuncSetAttribute(gemm_mma<3>, cudaFuncAttributeMaxDynamicSharedMemorySize,
                             3 * 4 * TILE_B);
        attr_done = true;
    }

    const dim3 blk(256);

    // 1) prep: split x; split Wq, Wk (UNtransposed, for M^T GEMM); transpose-split Wv
    split_f16<<<NT * DD / 512, blk>>>(x, xh, xl, NT * DD);
    split_f16<<<DD * DD / 512, blk>>>(wq, wh + 0 * WW, wl + 0 * WW, DD * DD);
    split_f16<<<DD * DD / 512, blk>>>(wk, wh + 1 * WW, wl + 1 * WW, DD * DD);
    tsplit_f16<<<dim3(DD / 32, DD / 32), blk>>>(wv, wh + 2 * WW, wl + 2 * WW, DD, DD);

    // 2) fused prep GEMM: V = x@Wv (fp32) and M^T = Wk@Wq^T (split fp16)
    gemm_mma<2><<<dim3(DD / 128, NT / 128 + DD / 128), blk, 3 * 4 * TILE_B>>>(
        nullptr, nullptr, nullptr, nullptr, nullptr, 0, DD, DD, 1.0f);

    // 3) V^T fp16 (hi only)
    t_h16<<<dim3(DD / 32, NT / 32), blk>>>(V, Vth, NT, DD);

    // 4) T = x @ M  (3-term; split-store Th/Tl)
    gemm_mma<3><<<dim3(DD / 128, NT / 128), blk, 3 * 4 * TILE_B>>>(
        xh, xl, MTh, MTl, nullptr, NT, DD, DD, 1.0f);

    // 5) scores: S = (T @ x^T) / 32   (3-term)
    gemm_mma<0><<<dim3(NT / 128, NT / 128), blk, 3 * 4 * TILE_B>>>(
        Th, Tl, xh, xl, S, NT, NT, DD, 1.0f / 32.0f);

    // 6) softmax -> P fp16
    softmax_f16<<<NT, blk>>>(S, Ph);

    // 7) out = P @ V   (1-term; B = V^T [1024, 4096])
    gemm_mma<1><<<dim3(DD / 128, NT / 128), blk, 3 * 2 * TILE_B>>>(
        Ph, nullptr, Vth, nullptr, out, NT, DD, NT, 1.0f);
}

// round 10
// speedup vs baseline: 4.0468x; 1.0046x over previous
#include <cuda_runtime.h>
#include <cuda_fp16.h>
#include <cstdint>

static constexpr int NT = 4096;   // tokens
static constexpr int DD = 1024;   // d_in == d_out
static constexpr size_t WW = (size_t)DD * DD;

// ---------------- scratch (__device__ globals: allocation-free rule) --------
__device__ float g_V[(size_t)NT * DD];              // fp32 V from prep epilogue
__device__ float g_S[(size_t)NT * NT];              // fp32 scores

__device__ __half g_xh[(size_t)NT * DD], g_xl[(size_t)NT * DD];
// region 0: Wq (untransposed) | region 1: Wk (untransposed) | region 2: Wv^T
__device__ __half g_wh[(size_t)3 * DD * DD], g_wl[(size_t)3 * DD * DD];
__device__ __half g_Th[(size_t)NT * DD], g_Tl[(size_t)NT * DD];           // T = x@M
__device__ __half g_MTh[(size_t)DD * DD], g_MTl[(size_t)DD * DD];         // M^T
__device__ __half g_Vth[(size_t)DD * NT];                                 // V^T fp16
__device__ __half g_Ph[(size_t)NT * NT];                                  // P fp16

// ---------------- helpers ---------------------------------------------------
__device__ __forceinline__ uint32_t smem_u32(const void* p) {
    uint32_t a;
    asm("{ .reg .u64 t; cvta.to.shared.u64 t, %1; cvt.u32.u64 %0, t; }"
        : "=r"(a) : "l"(p));
    return a;
}

// 128B-row swizzle: XOR 16B-chunk index (bits 4-6) with row%8 (bits 7-9)
#define SWZ(o) ((o) ^ ((((uint32_t)(o)) >> 3) & 0x70))

__device__ __forceinline__ void cp16(uint32_t saddr, const void* gaddr) {
    asm volatile("cp.async.cg.shared.global [%0], [%1], 16;"
                 :: "r"(saddr), "l"(gaddr));
}

__device__ __forceinline__ void ldm_x4(uint32_t* r, uint32_t addr) {
    asm volatile("ldmatrix.sync.aligned.m8n8.x4.shared.b16 {%0,%1,%2,%3}, [%4];"
                 : "=r"(r[0]), "=r"(r[1]), "=r"(r[2]), "=r"(r[3]) : "r"(addr));
}

__device__ __forceinline__ void mma_f16(float* c, const uint32_t* a, const uint32_t* b) {
    asm volatile(
        "mma.sync.aligned.m16n8k16.row.col.f32.f16.f16.f32 "
        "{%0,%1,%2,%3}, {%4,%5,%6,%7}, {%8,%9}, {%0,%1,%2,%3};"
        : "+f"(c[0]), "+f"(c[1]), "+f"(c[2]), "+f"(c[3])
        : "r"(a[0]), "r"(a[1]), "r"(a[2]), "r"(a[3]), "r"(b[0]), "r"(b[1]));
}

__device__ __forceinline__ void split_store_f16(
    __half* H, __half* L, size_t idx, float a, float b)
{
    const __half h0 = __float2half_rn(a);
    const __half h1 = __float2half_rn(b);
    const __half l0 = __float2half_rn(a - __half2float(h0));
    const __half l1 = __float2half_rn(b - __half2float(h1));
    *reinterpret_cast<__half2*>(H + idx) = __halves2half2(h0, h1);
    *reinterpret_cast<__half2*>(L + idx) = __halves2half2(l0, l1);
}

// ---------------------------------------------------------------------------
// Warp-MMA split-fp16 GEMM, BK=64, 3-stage cp.async pipeline.
//  MODE 0 (scores): C = alpha*(A@B^T); 3 terms; tiles A0,A1,B0,B1; fp32 C.
//  MODE 1 (PV):     C = A@B^T; 1 term; tiles A0,B0; fp32 C; occupancy 2.
//  MODE 2 (prep, fused grid):
//     by <  32: V = x @ Wv  (2 terms) -> g_V fp32
//     by >= 32: M^T = Wk @ Wq^T (3 terms; both UNtransposed) -> split store
//  MODE 3 (T):      T = x @ M (3 terms) -> g_Th/g_Tl split
// BM=BN=128, BK=64, 256 threads, 2(m)x4(n) warps, 64x32 warp tile.
// ---------------------------------------------------------------------------
static constexpr int TILE_B = 128 * 128;   // 16 KB (128 rows x 64 fp16)

template <int MODE>
__global__ __launch_bounds__(256, (MODE == 1) ? 2 : 1)
void gemm_mma(const __half* __restrict__ A0, const __half* __restrict__ A1,
              const __half* __restrict__ B0, const __half* __restrict__ B1,
              float* __restrict__ C, int M, int N, int K, float alpha)
{
    constexpr int NTILES  = (MODE == 1) ? 2 : 4;
    constexpr int STAGE_B = NTILES * TILE_B;

    extern __shared__ char smem[];
    const uint32_t sb = smem_u32(smem);
    const int tid  = threadIdx.x;
    const int wid  = tid >> 5;
    const int lane = tid & 31;

    const bool isM = (MODE == 2) && (blockIdx.y >= 32);   // M^T region of prep
    const int bm = (MODE == 2 && isM) ? (blockIdx.y - 32) * 128 : blockIdx.y * 128;
    const int bn = blockIdx.x * 128;
    const int wm = (wid >> 2) * 64;
    const int wn = (wid & 3) * 32;

    // third term (A1*B0) usage
    const bool t3 = (MODE == 0) || (MODE == 3) || (MODE == 2 && isM);

    const __half* srcs[4];
    int rbs[4];
    if (MODE == 1) {
        srcs[0] = A0; rbs[0] = bm;
        srcs[1] = B0; rbs[1] = bn;
        srcs[2] = nullptr; rbs[2] = 0;
        srcs[3] = nullptr; rbs[3] = 0;
    } else if (MODE == 2) {
        if (isM) {      // A = Wk splits, B = Wq splits (both untransposed)
            srcs[0] = g_wh + WW; srcs[1] = g_wl + WW;
            srcs[2] = g_wh;      srcs[3] = g_wl;
        } else {        // A = xh (2-term), B = Wv^T splits
            srcs[0] = g_xh;          srcs[1] = nullptr;
            srcs[2] = g_wh + 2 * WW; srcs[3] = g_wl + 2 * WW;
        }
        rbs[0] = bm; rbs[1] = bm; rbs[2] = bn; rbs[3] = bn;
    } else {
        srcs[0] = A0; rbs[0] = bm;
        srcs[1] = A1; rbs[1] = bm;
        srcs[2] = B0; rbs[2] = bn;
        srcs[3] = B1; rbs[3] = bn;
    }

    auto issue = [&](int stage, int kchunk) {
#pragma unroll
        for (int t = 0; t < NTILES; t++) {
            if (MODE == 2 && t == 1 && !t3) continue;   // V region: skip A1 tile
#pragma unroll
            for (int u = 0; u < 4; u++) {
                const int v = tid + 256 * u;            // 0..1023
                const int row = v >> 3, c16 = v & 7;
                const uint32_t o = (uint32_t)(row * 128 + c16 * 16);
                cp16(sb + stage * STAGE_B + t * TILE_B + SWZ(o),
                     srcs[t] + (size_t)(rbs[t] + row) * K + kchunk * 64 + c16 * 8);
            }
        }
        asm volatile("cp.async.commit_group;");
    };

    float acc[4][4][4];
#pragma unroll
    for (int i = 0; i < 4; i++)
#pragma unroll
        for (int j = 0; j < 4; j++)
#pragma unroll
            for (int r = 0; r < 4; r++) acc[i][j][r] = 0.0f;

    const int nc = K / 64;
    issue(0, 0);
    issue(1, 1);

    const int arow   = lane & 15;
    const int achunk = lane >> 4;
    const int bsub   = lane >> 3;
    const int brow   = (lane & 7) + (bsub >> 1) * 8;
    const int bchunk = bsub & 1;

    for (int i = 0; i < nc; i++) {
        if (i < nc - 1) asm volatile("cp.async.wait_group 1;");
        else            asm volatile("cp.async.wait_group 0;");
        __syncthreads();

        if (i + 2 < nc) issue((i + 2) % 3, i + 2);

        const uint32_t base = sb + (i % 3) * STAGE_B;
        const int bt0 = (MODE == 1) ? 1 : 2;
#pragma unroll
        for (int s = 0; s < 4; s++) {                  // 4 x k16 per BK=64 chunk
            uint32_t a0[4][4], a1[4][4], b0r[4][2], b1r[4][2];
#pragma unroll
            for (int t = 0; t < 4; t++) {
                const uint32_t o =
                    (uint32_t)((wm + t * 16 + arow) * 128 + (s * 2 + achunk) * 16);
                ldm_x4(a0[t], base + SWZ(o));
                if (MODE != 1) {
                    if (t3) ldm_x4(a1[t], base + TILE_B + SWZ(o));
                }
            }
#pragma unroll
            for (int g = 0; g < 2; g++) {
                const uint32_t o =
                    (uint32_t)((wn + g * 16 + brow) * 128 + (s * 2 + bchunk) * 16);
                uint32_t r[4];
                ldm_x4(r, base + bt0 * TILE_B + SWZ(o));
                b0r[2 * g][0] = r[0]; b0r[2 * g][1] = r[1];
                b0r[2 * g + 1][0] = r[2]; b0r[2 * g + 1][1] = r[3];
                if (MODE != 1) {
                    ldm_x4(r, base + (bt0 + 1) * TILE_B + SWZ(o));
                    b1r[2 * g][0] = r[0]; b1r[2 * g][1] = r[1];
                    b1r[2 * g + 1][0] = r[2]; b1r[2 * g + 1][1] = r[3];
                }
            }
#pragma unroll
            for (int mt = 0; mt < 4; mt++)
#pragma unroll
                for (int nt = 0; nt < 4; nt++) {
                    mma_f16(acc[mt][nt], a0[mt], b0r[nt]);
                    if (MODE != 1) {
                        mma_f16(acc[mt][nt], a0[mt], b1r[nt]);
                        if (t3) mma_f16(acc[mt][nt], a1[mt], b0r[nt]);
                    }
                }
        }
    }

    // ---- epilogue ----
    const int r0 = bm + wm + (lane >> 2);
    const int c0 = wn + (lane & 3) * 2;

    if (MODE == 2) {
#pragma unroll
        for (int mt = 0; mt < 4; mt++)
#pragma unroll
            for (int nt = 0; nt < 4; nt++) {
                const int row = r0 + mt * 16;
                const int col = bn + c0 + nt * 8;
                const size_t i0 = (size_t)row * DD + col;
                const size_t i1 = (size_t)(row + 8) * DD + col;
                if (isM) {
                    split_store_f16(g_MTh, g_MTl, i0, acc[mt][nt][0], acc[mt][nt][1]);
                    split_store_f16(g_MTh, g_MTl, i1, acc[mt][nt][2], acc[mt][nt][3]);
                } else {
                    *reinterpret_cast<float2*>(g_V + i0) =
                        make_float2(acc[mt][nt][0], acc[mt][nt][1]);
                    *reinterpret_cast<float2*>(g_V + i1) =
                        make_float2(acc[mt][nt][2], acc[mt][nt][3]);
                }
            }
    } else if (MODE == 3) {
#pragma unroll
        for (int mt = 0; mt < 4; mt++)
#pragma unroll
            for (int nt = 0; nt < 4; nt++) {
                const int row = r0 + mt * 16;
                const int col = bn + c0 + nt * 8;
                split_store_f16(g_Th, g_Tl, (size_t)row * DD + col,
                                acc[mt][nt][0], acc[mt][nt][1]);
                split_store_f16(g_Th, g_Tl, (size_t)(row + 8) * DD + col,
                                acc[mt][nt][2], acc[mt][nt][3]);
            }
    } else {
#pragma unroll
        for (int mt = 0; mt < 4; mt++)
#pragma unroll
            for (int nt = 0; nt < 4; nt++) {
                const int row = r0 + mt * 16;
                const int col = bn + c0 + nt * 8;
                *reinterpret_cast<float2*>(C + (size_t)row * N + col) =
                    make_float2(acc[mt][nt][0] * alpha, acc[mt][nt][1] * alpha);
                *reinterpret_cast<float2*>(C + (size_t)(row + 8) * N + col) =
                    make_float2(acc[mt][nt][2] * alpha, acc[mt][nt][3] * alpha);
            }
    }
}

// ---------------------------------------------------------------------------
// fused hi/lo fp16 splits: z=0 -> x [NT*DD], z=1 -> Wq, z=2 -> Wk  [DD*DD]
// ---------------------------------------------------------------------------
__global__ __launch_bounds__(256)
void split3_f16(const float* __restrict__ x, const float* __restrict__ wq,
                const float* __restrict__ wk)
{
    const int z = blockIdx.y;
    const float* in = (z == 0) ? x : (z == 1) ? wq : wk;
    __half* hi = (z == 0) ? g_xh : (z == 1) ? g_wh : g_wh + WW;
    __half* lo = (z == 0) ? g_xl : (z == 1) ? g_wl : g_wl + WW;
    const int n = (z == 0) ? NT * DD : DD * DD;

    const int idx = (blockIdx.x * 256 + threadIdx.x) * 2;
    if (idx < n) {
        const float2 v = *reinterpret_cast<const float2*>(in + idx);
        split_store_f16(hi, lo, idx, v.x, v.y);
    }
}

// ---------------------------------------------------------------------------
// fp32 [R,C] -> transposed (hi,lo) fp16 [C,R]   (Wv -> Wv^T)
// ---------------------------------------------------------------------------
__global__ __launch_bounds__(256)
void tsplit_f16(const float* __restrict__ in,
                __half* __restrict__ oh, __half* __restrict__ ol, int R, int C)
{
    __shared__ float t[32][33];
    const int bx = blockIdx.x * 32, by = blockIdx.y * 32;
    const int tx = threadIdx.x & 31, ty = threadIdx.x >> 5;
#pragma unroll
    for (int j = 0; j < 32; j += 8)
        t[ty + j][tx] = in[(size_t)(by + ty + j) * C + bx + tx];
    __syncthreads();
#pragma unroll
    for (int j = 0; j < 32; j += 8) {
        const float v = t[tx][ty + j];
        const __half h = __float2half_rn(v);
        const size_t o = (size_t)(bx + ty + j) * R + by + tx;
        oh[o] = h;
        ol[o] = __float2half_rn(v - __half2float(h));
    }
}

// ---------------------------------------------------------------------------
// fp32 [R,C] -> transposed fp16 [C,R], hi only   (V -> V^T)
// ---------------------------------------------------------------------------
__global__ __launch_bounds__(256)
void t_h16(const float* __restrict__ in, __half* __restrict__ oh, int R, int C)
{
    __shared__ float t[32][33];
    const int bx = blockIdx.x * 32, by = blockIdx.y * 32;
    const int tx = threadIdx.x & 31, ty = threadIdx.x >> 5;
#pragma unroll
    for (int j = 0; j < 32; j += 8)
        t[ty + j][tx] = in[(size_t)(by + ty + j) * C + bx + tx];
    __syncthreads();
#pragma unroll
    for (int j = 0; j < 32; j += 8) {
        const float v = t[tx][ty + j];
        oh[(size_t)(bx + ty + j) * R + by + tx] = __float2half_rn(v);
    }
}

// ---------------------------------------------------------------------------
// Row softmax over S[4096][4096] -> P fp16, with exp-skip:
// elements < rowmax-20 contribute exp ~ e^-20 (< 2^-24, rounds to 0 in fp16;
// sum deficit <= 4096*e^-20 ~ 8e-6 rel) -> threads whose whole 16-elem chunk
// is below the cutoff write zeros without touching MUFU.
// ---------------------------------------------------------------------------
__global__ __launch_bounds__(256)
void softmax_f16(const float* __restrict__ S, __half* __restrict__ Ph)
{
    const int row = blockIdx.x;
    const float* p = S + (size_t)row * NT;
    const int tid = threadIdx.x;
    const int base = tid * 16;

    float v[16];
#pragma unroll
    for (int q = 0; q < 4; q++) {
        const float4 x4 = *reinterpret_cast<const float4*>(p + base + q * 4);
        v[q * 4 + 0] = x4.x; v[q * 4 + 1] = x4.y; v[q * 4 + 2] = x4.z; v[q * 4 + 3] = x4.w;
    }

    __shared__ float red[256];
    float tmax = v[0];
#pragma unroll
    for (int q = 1; q < 16; q++) tmax = fmaxf(tmax, v[q]);
    red[tid] = tmax;
    __syncthreads();
#pragma unroll
    for (int s = 128; s > 0; s >>= 1) {
        if (tid < s) red[tid] = fmaxf(red[tid], red[tid + s]);
        __syncthreads();
    }
    const float m = red[0];
    __syncthreads();

    const float cut = m - 20.0f;
    const bool active = (tmax >= cut);

    float sum = 0.0f;
    if (active) {
#pragma unroll
        for (int q = 0; q < 16; q++) {
            v[q] = (v[q] >= cut) ? __expf(v[q] - m) : 0.0f;
            sum += v[q];
        }
    }
    red[tid] = sum;
    __syncthreads();
#pragma unroll
    for (int s = 128; s > 0; s >>= 1) {
        if (tid < s) red[tid] += red[tid + s];
        __syncthreads();
    }
    const float inv = 1.0f / red[0];

    __half* ph = Ph + (size_t)row * NT + base;
    if (active) {
#pragma unroll
        for (int q = 0; q < 8; q++) {
            *reinterpret_cast<__half2*>(ph + 2 * q) =
                __floats2half2_rn(v[2 * q] * inv, v[2 * q + 1] * inv);
        }
    } else {
        const __half2 z = __floats2half2_rn(0.0f, 0.0f);
#pragma unroll
        for (int q = 0; q < 8; q++)
            *reinterpret_cast<__half2*>(ph + 2 * q) = z;
    }
}

// ---------------------------------------------------------------------------
// kernel_launch
// ---------------------------------------------------------------------------
extern "C" void kernel_launch(void* const* d_in, const int* in_sizes, int n_in,
                              void* d_out, int out_size)
{
    const float* x  = (const float*)d_in[0];
    const float* wq = (const float*)d_in[1];
    const float* wk = (const float*)d_in[2];
    const float* wv = (const float*)d_in[3];
    float* out = (float*)d_out;

    float *V, *S;
    __half *xh, *xl, *wh, *wl, *Th, *Tl, *MTh, *MTl, *Vth, *Ph;
    cudaGetSymbolAddress((void**)&V, g_V);
    cudaGetSymbolAddress((void**)&S, g_S);
    cudaGetSymbolAddress((void**)&xh, g_xh);
    cudaGetSymbolAddress((void**)&xl, g_xl);
    cudaGetSymbolAddress((void**)&wh, g_wh);
    cudaGetSymbolAddress((void**)&wl, g_wl);
    cudaGetSymbolAddress((void**)&Th, g_Th);
    cudaGetSymbolAddress((void**)&Tl, g_Tl);
    cudaGetSymbolAddress((void**)&MTh, g_MTh);
    cudaGetSymbolAddress((void**)&MTl, g_MTl);
    cudaGetSymbolAddress((void**)&Vth, g_Vth);
    cudaGetSymbolAddress((void**)&Ph, g_Ph);

    static bool attr_done = false;
    if (!attr_done) {
        cudaFuncSetAttribute(gemm_mma<0>, cudaFuncAttributeMaxDynamicSharedMemorySize,
                             3 * 4 * TILE_B);
        cudaFuncSetAttribute(gemm_mma<1>, cudaFuncAttributeMaxDynamicSharedMemorySize,
                             3 * 2 * TILE_B);
        cudaFuncSetAttribute(gemm_mma<2>, cudaFuncAttributeMaxDynamicSharedMemorySize,
                             3 * 4 * TILE_B);
        cudaFuncSetAttribute(gemm_mma<3>, cudaFuncAttributeMaxDynamicSharedMemorySize,
                             3 * 4 * TILE_B);
        attr_done = true;
    }

    const dim3 blk(256);

    // 1) prep: fused splits of x, Wq, Wk (untransposed) + transpose-split Wv
    split3_f16<<<dim3(NT * DD / 512, 3), blk>>>(x, wq, wk);
    tsplit_f16<<<dim3(DD / 32, DD / 32), blk>>>(wv, wh + 2 * WW, wl + 2 * WW, DD, DD);

    // 2) fused prep GEMM: V = x@Wv (fp32) and M^T = Wk@Wq^T (split fp16)
    gemm_mma<2><<<dim3(DD / 128, NT / 128 + DD / 128), blk, 3 * 4 * TILE_B>>>(
        nullptr, nullptr, nullptr, nullptr, nullptr, 0, DD, DD, 1.0f);

    // 3) V^T fp16 (hi only)
    t_h16<<<dim3(DD / 32, NT / 32), blk>>>(V, Vth, NT, DD);

    // 4) T = x @ M  (3-term; split-store Th/Tl)
    gemm_mma<3><<<dim3(DD / 128, NT / 128), blk, 3 * 4 * TILE_B>>>(
        xh, xl, MTh, MTl, nullptr, NT, DD, DD, 1.0f);

    // 5) scores: S = (T @ x^T) / 32   (3-term)
    gemm_mma<0><<<dim3(NT / 128, NT / 128), blk, 3 * 4 * TILE_B>>>(
        Th, Tl, xh, xl, S, NT, NT, DD, 1.0f / 32.0f);

    // 6) softmax -> P fp16 (exp-skip)
    softmax_f16<<<NT, blk>>>(S, Ph);

    // 7) out = P @ V   (1-term; occupancy 2; B = V^T [1024, 4096])
    gemm_mma<1><<<dim3(DD / 128, NT / 128), blk, 3 * 2 * TILE_B>>>(
        Ph, nullptr, Vth, nullptr, out, NT, DD, NT, 1.0f);
}